// round 13
// baseline (speedup 1.0000x reference)
#include <cuda_runtime.h>
#include <cuda_bf16.h>
#include <cstdint>
#include <math.h>

#define Hh 12
#define Ee 768
#define Dd 64
#define LLen 2048
#define Bb 2
#define Mrows (Bb*LLen)      // 4096
#define N3E (3*Ee)           // 2304
#define LORA 8.0f
#define LOG2E 1.44269504088896340736f

// ---------------- scratch ----------------
__device__ __nv_bfloat16 g_w1h[N3E * Ee], g_w1l[N3E * Ee];
__device__ __nv_bfloat16 g_w2h[Ee * Ee],  g_w2l[Ee * Ee];
__device__ __nv_bfloat16 g_xh [Mrows * Ee], g_xl [Mrows * Ee];
__device__ float g_c [Mrows * N3E];                  // qkv; q-region pre-scaled by log2e, tf32-rounded
__device__ float g_vt[Bb * Hh * Dd * LLen];          // V transposed: [bh*64+d][token]
__device__ __nv_bfloat16 g_ah [Mrows * Ee], g_al [Mrows * Ee];
// split-KV partials: 24 bh x 16 qt x up-to-4 chunks
__device__ float g_pm[1536 * 128];
__device__ float g_pl[1536 * 128];
__device__ float g_po[1536 * 128 * 64];

// work-item tables: 40 items per bh, heavy-first. item -> (qt, start tile)
__device__ const int d_jqt[40] = {15,15,15,15, 14,14,14,14, 13,13,13,13, 12,12,12,12,
                                  11,11,11, 10,10,10, 9,9,9, 8,8,8,
                                  7,7, 6,6, 5,5, 4,4, 3, 2, 1, 0};
__device__ const int d_jc0[40] = {0,8,16,24, 0,8,16,24, 0,8,16,24, 0,8,16,24,
                                  0,8,16, 0,8,16, 0,8,16, 0,8,16,
                                  0,8, 0,8, 0,8, 0,8, 0, 0, 0, 0};
__device__ const int d_nc[16]  = {1,1,1,1, 2,2,2,2, 3,3,3,3, 4,4,4,4};

// =================== helpers ===================
__device__ __forceinline__ uint32_t smem_u32(const void* p) {
    uint32_t a;
    asm("{ .reg .u64 t; cvta.to.shared.u64 t, %1; cvt.u32.u64 %0, t; }" : "=r"(a) : "l"(p));
    return a;
}
__device__ __forceinline__ float rna(float x) {
    uint32_t r;
    asm("cvt.rna.tf32.f32 %0, %1;" : "=r"(r) : "f"(x));
    return __uint_as_float(r);
}
__device__ __forceinline__ float ex2(float x) {
    float r;
    asm("ex2.approx.f32 %0, %1;" : "=f"(r) : "f"(x));
    return r;
}
__device__ __forceinline__ void cp16(uint32_t dst, const void* src) {
    asm volatile("cp.async.cg.shared.global [%0], [%1], 16;" :: "r"(dst), "l"(src));
}
#define CP_COMMIT() asm volatile("cp.async.commit_group;" ::: "memory")

__device__ __forceinline__ void ldsm4(uint32_t& r0, uint32_t& r1, uint32_t& r2, uint32_t& r3,
                                      uint32_t addr) {
    asm volatile("ldmatrix.sync.aligned.m8n8.x4.shared.b16 {%0,%1,%2,%3}, [%4];"
                 : "=r"(r0), "=r"(r1), "=r"(r2), "=r"(r3) : "r"(addr));
}
__device__ __forceinline__ void mma_tf32(float* c, uint32_t a0, uint32_t a1, uint32_t a2,
                                         uint32_t a3, uint32_t b0, uint32_t b1) {
    asm volatile("mma.sync.aligned.m16n8k8.row.col.f32.tf32.tf32.f32 "
                 "{%0,%1,%2,%3}, {%4,%5,%6,%7}, {%8,%9}, {%0,%1,%2,%3};"
                 : "+f"(c[0]), "+f"(c[1]), "+f"(c[2]), "+f"(c[3])
                 : "r"(a0), "r"(a1), "r"(a2), "r"(a3), "r"(b0), "r"(b1));
}
__device__ __forceinline__ void mma_bf16(float* c, uint32_t a0, uint32_t a1, uint32_t a2,
                                         uint32_t a3, uint32_t b0, uint32_t b1) {
    asm volatile("mma.sync.aligned.m16n8k16.row.col.f32.bf16.bf16.f32 "
                 "{%0,%1,%2,%3}, {%4,%5,%6,%7}, {%8,%9}, {%0,%1,%2,%3};"
                 : "+f"(c[0]), "+f"(c[1]), "+f"(c[2]), "+f"(c[3])
                 : "r"(a0), "r"(a1), "r"(a2), "r"(a3), "r"(b0), "r"(b1));
}
__device__ __forceinline__ void bf16_split(float f, __nv_bfloat16& h, __nv_bfloat16& l) {
    h = __float2bfloat16(f);
    l = __float2bfloat16(f - __bfloat162float(h));
}

// ---------------- prep (merged): wt = (w + 8*B@A)^T split into bf16 hi/lo ----------------
__global__ void prep_wt2(const float* __restrict__ w1, const float* __restrict__ A1,
                         const float* __restrict__ B1, __nv_bfloat16* __restrict__ w1h,
                         __nv_bfloat16* __restrict__ w1l,
                         const float* __restrict__ w2, const float* __restrict__ A2,
                         const float* __restrict__ B2, __nv_bfloat16* __restrict__ w2h,
                         __nv_bfloat16* __restrict__ w2l)
{
    const int z = blockIdx.z;
    const float* w  = z ? w2 : w1;
    const float* Aa = z ? A2 : A1;
    const float* Bm = z ? B2 : B1;
    __nv_bfloat16* wh = z ? w2h : w1h;
    __nv_bfloat16* wl = z ? w2l : w1l;
    const int ncols = z ? Ee : N3E;

    __shared__ float t[32][33];
    int o0 = blockIdx.x * 32, e0 = blockIdx.y * 32;
    if (o0 >= ncols) return;
    int tx = threadIdx.x, ty = threadIdx.y;
    #pragma unroll
    for (int r = 0; r < 4; r++) {
        int e = e0 + ty + r * 8, o = o0 + tx;
        float s = 0.f;
        #pragma unroll
        for (int q = 0; q < 4; q++) s += Bm[e*4 + q] * Aa[q*ncols + o];
        t[ty + r*8][tx] = w[(size_t)e * ncols + o] + LORA * s;
    }
    __syncthreads();
    #pragma unroll
    for (int r = 0; r < 4; r++) {
        int o = o0 + ty + r * 8, e = e0 + tx;
        __nv_bfloat16 hh, ll;
        bf16_split(t[tx][ty + r*8], hh, ll);
        wh[(size_t)o * Ee + e] = hh;
        wl[(size_t)o * Ee + e] = ll;
    }
}

// ---------------- x -> bf16 hi/lo split ----------------
__global__ void cvt_x(const float4* __restrict__ in, __nv_bfloat16* __restrict__ oh,
                      __nv_bfloat16* __restrict__ ol)
{
    int i = blockIdx.x * blockDim.x + threadIdx.x;
    float4 v = in[i];
    __nv_bfloat16 h0,l0,h1,l1,h2,l2,h3,l3;
    bf16_split(v.x, h0, l0); bf16_split(v.y, h1, l1);
    bf16_split(v.z, h2, l2); bf16_split(v.w, h3, l3);
    int o = i * 4;
    *(__nv_bfloat162*)&oh[o]     = __nv_bfloat162(h0, h1);
    *(__nv_bfloat162*)&oh[o + 2] = __nv_bfloat162(h2, h3);
    *(__nv_bfloat162*)&ol[o]     = __nv_bfloat162(l0, l1);
    *(__nv_bfloat162*)&ol[o + 2] = __nv_bfloat162(l2, l3);
}

// ---------------- V transpose: g_c v-region -> g_vt[bh*64+d][token] ----------------
__global__ void vtrans()
{
    __shared__ float t[32][33];
    const int bh   = blockIdx.y >> 1;
    const int dblk = (blockIdx.y & 1) * 32;
    const int tok0 = blockIdx.x * 32;
    const int b = bh / Hh, h = bh - b * Hh;
    const int tx = threadIdx.x, ty = threadIdx.y;
    const float* src = g_c + (size_t)(b * LLen) * N3E + 2 * Ee + h * Dd;
    #pragma unroll
    for (int r = 0; r < 4; r++) {
        int token = tok0 + ty + r * 8;
        t[ty + r*8][tx] = src[(size_t)token * N3E + dblk + tx];
    }
    __syncthreads();
    #pragma unroll
    for (int r = 0; r < 4; r++) {
        int d = dblk + ty + r * 8;
        g_vt[(size_t)(bh * Dd + d) * LLen + tok0 + tx] = t[tx][ty + r*8];
    }
}

// ---------------- bf16x2 mma.sync GEMM: C = A*Wt^T + bias (3-product split-2) ----------------
#define NTk 24   // 768/32

template<int TN, bool RNA>
__global__ void __launch_bounds__(256, 2)
gemm_tc(const __nv_bfloat16* __restrict__ Ah, const __nv_bfloat16* __restrict__ Al,
        const __nv_bfloat16* __restrict__ Wh, const __nv_bfloat16* __restrict__ Wl,
        const float* __restrict__ bias, float* __restrict__ C, int N)
{
    constexpr int MT = (TN == 128) ? 4 : 2;
    constexpr int WM = 128 / (MT * 16);
    constexpr int ABY = 128 * 64;
    constexpr int BBY = TN * 64;
    constexpr int SBYTES = 2 * ABY + 2 * BBY;
    constexpr int STG = (TN == 128) ? 3 : 4;

    extern __shared__ float sm[];
    const uint32_t sbase = smem_u32(sm);

    const int tid  = threadIdx.x;
    const int wid  = tid >> 5;
    const int lane = tid & 31;
    const int m0 = blockIdx.y * 128;
    const int n0 = blockIdx.x * TN;
    const int wm = wid & (WM - 1);
    const int wn = wid / WM;

    auto load_tile = [&](int kt) {
        const int st = kt % STG;
        const uint32_t sAh = sbase + st * SBYTES;
        const uint32_t sAl = sAh + ABY;
        const uint32_t sBh = sAl + ABY;
        const uint32_t sBl = sBh + BBY;
        const __nv_bfloat16* Agh = Ah + (size_t)m0 * Ee + kt * 32;
        const __nv_bfloat16* Agl = Al + (size_t)m0 * Ee + kt * 32;
        const __nv_bfloat16* Bgh = Wh + (size_t)n0 * Ee + kt * 32;
        const __nv_bfloat16* Bgl = Wl + (size_t)n0 * Ee + kt * 32;
        #pragma unroll
        for (int i = 0; i < 2; i++) {
            int f = tid + i * 256;
            int row = f >> 2, ch = f & 3;
            uint32_t off = row * 64 + ((ch ^ ((row >> 1) & 3)) << 4);
            cp16(sAh + off, Agh + (size_t)row * Ee + ch * 8);
            cp16(sAl + off, Agl + (size_t)row * Ee + ch * 8);
        }
        #pragma unroll
        for (int i = 0; i < TN / 64; i++) {
            int f = tid + i * 256;
            int row = f >> 2, ch = f & 3;
            uint32_t off = row * 64 + ((ch ^ ((row >> 1) & 3)) << 4);
            cp16(sBh + off, Bgh + (size_t)row * Ee + ch * 8);
            cp16(sBl + off, Bgl + (size_t)row * Ee + ch * 8);
        }
        CP_COMMIT();
    };

    float acc[MT][4][4];
    #pragma unroll
    for (int i = 0; i < MT; i++)
        #pragma unroll
        for (int j = 0; j < 4; j++)
            #pragma unroll
            for (int k = 0; k < 4; k++) acc[i][j][k] = 0.f;

    int arow[MT], bro[2];
    #pragma unroll
    for (int mt = 0; mt < MT; mt++) arow[mt] = wm * MT * 16 + mt * 16 + (lane & 15);
    const int achk = (lane >> 4) & 1;
    #pragma unroll
    for (int p = 0; p < 2; p++) bro[p] = wn * 32 + p * 16 + (lane & 7) + ((lane >> 4) & 1) * 8;
    const int bchk = (lane >> 3) & 1;

    #pragma unroll
    for (int kt = 0; kt < STG - 1; kt++) load_tile(kt);

    for (int it = 0; it < NTk; ++it) {
        const int st = it % STG;
        if (STG == 3) {
            if (it < NTk - 1) asm volatile("cp.async.wait_group 1;" ::: "memory");
            else              asm volatile("cp.async.wait_group 0;" ::: "memory");
        } else {
            if (it < NTk - 2)       asm volatile("cp.async.wait_group 2;" ::: "memory");
            else if (it == NTk - 2) asm volatile("cp.async.wait_group 1;" ::: "memory");
            else                    asm volatile("cp.async.wait_group 0;" ::: "memory");
        }
        __syncthreads();

        if (it + STG - 1 < NTk) load_tile(it + STG - 1);

        const uint32_t sAh = sbase + st * SBYTES;
        const uint32_t sAl = sAh + ABY;
        const uint32_t sBh = sAl + ABY;
        const uint32_t sBl = sBh + BBY;

        #pragma unroll
        for (int ks = 0; ks < 2; ks++) {
            uint32_t afh[MT][4];
            #pragma unroll
            for (int mt = 0; mt < MT; mt++)
                ldsm4(afh[mt][0], afh[mt][1], afh[mt][2], afh[mt][3],
                      sAh + arow[mt] * 64 + (((2*ks + achk) ^ ((arow[mt] >> 1) & 3)) << 4));
            uint32_t bfh[4][2];
            #pragma unroll
            for (int p = 0; p < 2; p++)
                ldsm4(bfh[2*p][0], bfh[2*p][1], bfh[2*p+1][0], bfh[2*p+1][1],
                      sBh + bro[p] * 64 + (((2*ks + bchk) ^ ((bro[p] >> 1) & 3)) << 4));
            #pragma unroll
            for (int mt = 0; mt < MT; mt++)
                #pragma unroll
                for (int nt = 0; nt < 4; nt++)
                    mma_bf16(acc[mt][nt], afh[mt][0], afh[mt][1], afh[mt][2], afh[mt][3],
                             bfh[nt][0], bfh[nt][1]);
            uint32_t bfl[4][2];
            #pragma unroll
            for (int p = 0; p < 2; p++)
                ldsm4(bfl[2*p][0], bfl[2*p][1], bfl[2*p+1][0], bfl[2*p+1][1],
                      sBl + bro[p] * 64 + (((2*ks + bchk) ^ ((bro[p] >> 1) & 3)) << 4));
            #pragma unroll
            for (int mt = 0; mt < MT; mt++)
                #pragma unroll
                for (int nt = 0; nt < 4; nt++)
                    mma_bf16(acc[mt][nt], afh[mt][0], afh[mt][1], afh[mt][2], afh[mt][3],
                             bfl[nt][0], bfl[nt][1]);
            uint32_t afl[MT][4];
            #pragma unroll
            for (int mt = 0; mt < MT; mt++)
                ldsm4(afl[mt][0], afl[mt][1], afl[mt][2], afl[mt][3],
                      sAl + arow[mt] * 64 + (((2*ks + achk) ^ ((arow[mt] >> 1) & 3)) << 4));
            #pragma unroll
            for (int mt = 0; mt < MT; mt++)
                #pragma unroll
                for (int nt = 0; nt < 4; nt++)
                    mma_bf16(acc[mt][nt], afl[mt][0], afl[mt][1], afl[mt][2], afl[mt][3],
                             bfh[nt][0], bfh[nt][1]);
        }
    }

    const int g = lane >> 2, t = lane & 3;
    // q-region of GEMM1 gets log2e folded in (softmax runs in log2 domain)
    const float qs = (RNA && n0 < Ee) ? LOG2E : 1.f;
    #pragma unroll
    for (int nt = 0; nt < 4; nt++) {
        const int col = n0 + wn * 32 + nt * 8 + 2 * t;
        float2 bz = *(const float2*)&bias[col];
        #pragma unroll
        for (int mt = 0; mt < MT; mt++) {
            const int r0 = m0 + wm * MT * 16 + mt * 16 + g;
            float2 v0, v1;
            if (RNA) {
                v0.x = rna(qs * (acc[mt][nt][0] + bz.x)); v0.y = rna(qs * (acc[mt][nt][1] + bz.y));
                v1.x = rna(qs * (acc[mt][nt][2] + bz.x)); v1.y = rna(qs * (acc[mt][nt][3] + bz.y));
            } else {
                v0.x = acc[mt][nt][0] + bz.x; v0.y = acc[mt][nt][1] + bz.y;
                v1.x = acc[mt][nt][2] + bz.x; v1.y = acc[mt][nt][3] + bz.y;
            }
            *(float2*)&C[(size_t)r0 * N + col]       = v0;
            *(float2*)&C[(size_t)(r0 + 8) * N + col] = v1;
        }
    }
}

// ---------------- flash attention: tf32 mma.sync, causal, fine split-KV ----------------
// v8: 40 work items per bh (<=8 KV tiles each), heavy-first; softmax in log2 domain.
// smem: Q 32KB @0 | K[2] 16KB @32K,48K | V[2] 16KB @64K,80K  = 96KB
__global__ void __launch_bounds__(256, 2)
flash_tc()
{
    extern __shared__ float smf[];
    const uint32_t QsB = smem_u32(smf);

    const int tid  = threadIdx.x;
    const int wid  = tid >> 5;
    const int lane = tid & 31;
    const int g = lane >> 2, t = lane & 3;

    const int slot = blockIdx.y;
    const int qt = d_jqt[slot];
    const int c0 = d_jc0[slot];
    const int nc = d_nc[qt];
    const int q0 = qt * 128;
    const int t0 = c0;
    const int t1 = min(c0 + 8, 2 * qt + 2);

    const int bh = blockIdx.x;
    const int b  = bh / Hh;
    const int h  = bh - b * Hh;

    const float* qg = g_c + (size_t)(b * LLen) * N3E + h * Dd;
    const float* kg = qg + Ee;
    const float* vt = g_vt + (size_t)bh * Dd * LLen;

    const int srow = tid >> 4;
    const int sch  = tid & 15;

    auto load_kv = [&](int kb, int buf) {
        const uint32_t KsB = QsB + 32768u + (uint32_t)buf * 16384u;
        const uint32_t VtB = QsB + 65536u + (uint32_t)buf * 16384u;
        #pragma unroll
        for (int i = 0; i < 4; i++) {
            int r = srow + i * 16;
            cp16(KsB + r * 256 + ((sch ^ ((r & 7) << 1)) << 4),
                 kg + (size_t)(kb + r) * N3E + sch * 4);
        }
        #pragma unroll
        for (int i = 0; i < 4; i++) {
            int d = srow + i * 16;
            cp16(VtB + d * 256 + ((sch ^ ((d & 7) << 1)) << 4),
                 vt + (size_t)d * LLen + kb + sch * 4);
        }
        CP_COMMIT();
    };

    // Q (already log2e-scaled + tf32-rounded in gmem)
    #pragma unroll
    for (int i = 0; i < 8; i++) {
        int r = srow + i * 16;
        cp16(QsB + r * 256 + ((sch ^ ((r & 7) << 1)) << 4),
             qg + (size_t)(q0 + r) * N3E + sch * 4);
    }
    load_kv(t0 * 64, t0 & 1);

    float m[2] = {-INFINITY, -INFINITY};
    float l[2] = {0.f, 0.f};
    float oacc[8][4];
    #pragma unroll
    for (int j = 0; j < 8; j++)
        #pragma unroll
        for (int k = 0; k < 4; k++) oacc[j][k] = 0.f;

    const int arow = (wid << 4) + (lane & 15);
    const int achk = (lane >> 4) & 1;
    const int asw  = (arow & 7) << 1;
    int brow[4];
    #pragma unroll
    for (int p = 0; p < 4; p++) brow[p] = (p << 4) + (lane & 7) + (((lane >> 4) & 1) << 3);
    const int bchk = (lane >> 3) & 1;

    const int srcA = (lane & ~3) | (t >> 1);
    const int srcB = srcA + 2;
    const bool odd = (t & 1);

    for (int ti = t0; ti < t1; ti++) {
        const int kb = ti * 64;
        const int buf = ti & 1;
        const uint32_t KsB = QsB + 32768u + (uint32_t)buf * 16384u;
        const uint32_t VtB = QsB + 65536u + (uint32_t)buf * 16384u;

        asm volatile("cp.async.wait_group 0;" ::: "memory");
        __syncthreads();
        if (ti + 1 < t1) load_kv(kb + 64, buf ^ 1);

        // fully-masked warp in final diagonal tile: skip compute (identical result)
        if (q0 + (wid << 4) + 15 < kb) continue;

        // ---- S' = (log2e*Q) K^T ----
        float sacc[8][4];
        #pragma unroll
        for (int j = 0; j < 8; j++)
            #pragma unroll
            for (int k = 0; k < 4; k++) sacc[j][k] = 0.f;

        #pragma unroll
        for (int ks = 0; ks < 8; ks++) {
            uint32_t a0, a1, a2, a3;
            ldsm4(a0, a1, a2, a3,
                  QsB + arow * 256 + ((((ks << 1) + achk) ^ asw) << 4));
            uint32_t bf[8][2];
            #pragma unroll
            for (int p = 0; p < 4; p++)
                ldsm4(bf[2*p][0], bf[2*p][1], bf[2*p+1][0], bf[2*p+1][1],
                      KsB + brow[p] * 256 + ((((ks << 1) + bchk) ^ ((brow[p] & 7) << 1)) << 4));
            #pragma unroll
            for (int j = 0; j < 8; j++)
                mma_tf32(sacc[j], a0, a1, a2, a3, bf[j][0], bf[j][1]);
        }

        // causal mask (diagonal tiles)
        if (kb >= q0) {
            const int r0g = q0 + (wid << 4) + g;
            #pragma unroll
            for (int j = 0; j < 8; j++) {
                int cg = kb + (j << 3) + (t << 1);
                if (cg > r0g)         sacc[j][0] = -1e9f;
                if (cg + 1 > r0g)     sacc[j][1] = -1e9f;
                if (cg > r0g + 8)     sacc[j][2] = -1e9f;
                if (cg + 1 > r0g + 8) sacc[j][3] = -1e9f;
            }
        }

        // ---- online softmax in log2 domain (rows g and g+8) ----
        float mt0 = -INFINITY, mt1 = -INFINITY;
        #pragma unroll
        for (int j = 0; j < 8; j++) {
            mt0 = fmaxf(mt0, fmaxf(sacc[j][0], sacc[j][1]));
            mt1 = fmaxf(mt1, fmaxf(sacc[j][2], sacc[j][3]));
        }
        mt0 = fmaxf(mt0, __shfl_xor_sync(0xffffffffu, mt0, 1));
        mt0 = fmaxf(mt0, __shfl_xor_sync(0xffffffffu, mt0, 2));
        mt1 = fmaxf(mt1, __shfl_xor_sync(0xffffffffu, mt1, 1));
        mt1 = fmaxf(mt1, __shfl_xor_sync(0xffffffffu, mt1, 2));
        float mn0 = fmaxf(m[0], mt0), mn1 = fmaxf(m[1], mt1);
        float sc0 = ex2(m[0] - mn0), sc1 = ex2(m[1] - mn1);
        m[0] = mn0; m[1] = mn1;
        float ls0 = 0.f, ls1 = 0.f;
        #pragma unroll
        for (int j = 0; j < 8; j++) {
            sacc[j][0] = rna(ex2(sacc[j][0] - mn0)); ls0 += sacc[j][0];
            sacc[j][1] = rna(ex2(sacc[j][1] - mn0)); ls0 += sacc[j][1];
            sacc[j][2] = rna(ex2(sacc[j][2] - mn1)); ls1 += sacc[j][2];
            sacc[j][3] = rna(ex2(sacc[j][3] - mn1)); ls1 += sacc[j][3];
        }
        ls0 += __shfl_xor_sync(0xffffffffu, ls0, 1);
        ls0 += __shfl_xor_sync(0xffffffffu, ls0, 2);
        ls1 += __shfl_xor_sync(0xffffffffu, ls1, 1);
        ls1 += __shfl_xor_sync(0xffffffffu, ls1, 2);
        l[0] = l[0] * sc0 + ls0;
        l[1] = l[1] * sc1 + ls1;
        #pragma unroll
        for (int j = 0; j < 8; j++) {
            oacc[j][0] *= sc0; oacc[j][1] *= sc0;
            oacc[j][2] *= sc1; oacc[j][3] *= sc1;
        }

        // ---- O += P V : P C-frag -> A-frag via shuffles, then MMA ----
        #pragma unroll
        for (int ks = 0; ks < 8; ks++) {
            float v0 = __shfl_sync(0xffffffffu, sacc[ks][0], srcA);
            float v1 = __shfl_sync(0xffffffffu, sacc[ks][1], srcA);
            float v2 = __shfl_sync(0xffffffffu, sacc[ks][2], srcA);
            float v3 = __shfl_sync(0xffffffffu, sacc[ks][3], srcA);
            float w0 = __shfl_sync(0xffffffffu, sacc[ks][0], srcB);
            float w1 = __shfl_sync(0xffffffffu, sacc[ks][1], srcB);
            float w2 = __shfl_sync(0xffffffffu, sacc[ks][2], srcB);
            float w3 = __shfl_sync(0xffffffffu, sacc[ks][3], srcB);
            uint32_t pa0 = __float_as_uint(odd ? v1 : v0);
            uint32_t pa1 = __float_as_uint(odd ? v3 : v2);
            uint32_t pa2 = __float_as_uint(odd ? w1 : w0);
            uint32_t pa3 = __float_as_uint(odd ? w3 : w2);

            uint32_t vf[8][2];
            #pragma unroll
            for (int p = 0; p < 4; p++)
                ldsm4(vf[2*p][0], vf[2*p][1], vf[2*p+1][0], vf[2*p+1][1],
                      VtB + brow[p] * 256 + ((((ks << 1) + bchk) ^ ((brow[p] & 7) << 1)) << 4));
            #pragma unroll
            for (int j = 0; j < 8; j++)
                mma_tf32(oacc[j], pa0, pa1, pa2, pa3, vf[j][0], vf[j][1]);
        }
    }

    const int lr0 = (wid << 4) + g;
    const int lr1 = lr0 + 8;
    if (nc > 1) {
        // ---- store unnormalized partial ----
        const int pidx = (bh * 16 + qt) * 4 + (c0 >> 3);
        float* po = g_po + (size_t)pidx * 128 * 64;
        #pragma unroll
        for (int j = 0; j < 8; j++) {
            int d = (j << 3) + (t << 1);
            *(float2*)&po[lr0 * 64 + d] = make_float2(oacc[j][0], oacc[j][1]);
            *(float2*)&po[lr1 * 64 + d] = make_float2(oacc[j][2], oacc[j][3]);
        }
        if (t == 0) {
            g_pm[pidx * 128 + lr0] = m[0]; g_pl[pidx * 128 + lr0] = l[0];
            g_pm[pidx * 128 + lr1] = m[1]; g_pl[pidx * 128 + lr1] = l[1];
        }
    } else {
        // ---- epilogue: normalize, split bf16 hi/lo, store ----
        const float inv0 = 1.f / l[0], inv1 = 1.f / l[1];
        const int grow = b * LLen + q0 + lr0;
        __nv_bfloat16* ah0 = g_ah + (size_t)grow * Ee + h * Dd;
        __nv_bfloat16* al0 = g_al + (size_t)grow * Ee + h * Dd;
        __nv_bfloat16* ah1 = ah0 + 8 * Ee;
        __nv_bfloat16* al1 = al0 + 8 * Ee;
        #pragma unroll
        for (int j = 0; j < 8; j++) {
            int d = (j << 3) + (t << 1);
            float o0 = oacc[j][0] * inv0, o1 = oacc[j][1] * inv0;
            float o2 = oacc[j][2] * inv1, o3 = oacc[j][3] * inv1;
            __nv_bfloat16 h0,l0b,h1,l1b,h2,l2b,h3,l3b;
            bf16_split(o0, h0, l0b); bf16_split(o1, h1, l1b);
            bf16_split(o2, h2, l2b); bf16_split(o3, h3, l3b);
            *(__nv_bfloat162*)&ah0[d] = __nv_bfloat162(h0, h1);
            *(__nv_bfloat162*)&al0[d] = __nv_bfloat162(l0b, l1b);
            *(__nv_bfloat162*)&ah1[d] = __nv_bfloat162(h2, h3);
            *(__nv_bfloat162*)&al1[d] = __nv_bfloat162(l2b, l3b);
        }
    }
}

// ---------------- merge split-KV partials (log2-domain m) ----------------
// grid (12, 24): x -> qt = 4+x, y = bh. 256 threads: row = tid/2, col half.
__global__ void merge_kv()
{
    const int qt = 4 + blockIdx.x;
    const int bh = blockIdx.y;
    const int nc = d_nc[qt];
    const int b = bh / Hh, h = bh - b * Hh;
    const int pbase = (bh * 16 + qt) * 4;
    const int r  = threadIdx.x >> 1;
    const int c0 = (threadIdx.x & 1) * 32;

    float mm = -INFINITY;
    for (int i = 0; i < nc; i++) mm = fmaxf(mm, g_pm[(pbase + i) * 128 + r]);

    float acc[32];
    #pragma unroll
    for (int c = 0; c < 32; c++) acc[c] = 0.f;
    float lt = 0.f;
    for (int i = 0; i < nc; i++) {
        float e = ex2(g_pm[(pbase + i) * 128 + r] - mm);
        lt += g_pl[(pbase + i) * 128 + r] * e;
        const float* oi = g_po + ((size_t)(pbase + i) * 128 + r) * 64 + c0;
        #pragma unroll
        for (int c = 0; c < 32; c += 2) {
            float2 v = *(const float2*)&oi[c];
            acc[c]   += v.x * e;
            acc[c+1] += v.y * e;
        }
    }
    float inv = 1.f / lt;

    const int grow = b * LLen + qt * 128 + r;
    __nv_bfloat16* ah = g_ah + (size_t)grow * Ee + h * Dd + c0;
    __nv_bfloat16* al = g_al + (size_t)grow * Ee + h * Dd + c0;
    #pragma unroll
    for (int c = 0; c < 32; c += 2) {
        float v0 = acc[c] * inv, v1 = acc[c+1] * inv;
        __nv_bfloat16 h0, l0, h1, l1b;
        bf16_split(v0, h0, l0); bf16_split(v1, h1, l1b);
        *(__nv_bfloat162*)&ah[c] = __nv_bfloat162(h0, h1);
        *(__nv_bfloat162*)&al[c] = __nv_bfloat162(l0, l1b);
    }
}

// ---------------- launch ----------------
extern "C" void kernel_launch(void* const* d_in, const int* in_sizes, int n_in,
                              void* d_out, int out_size)
{
    const float* x     = (const float*)d_in[0];
    const float* w_in  = (const float*)d_in[1];
    const float* b_in  = (const float*)d_in[2];
    const float* A_in  = (const float*)d_in[3];
    const float* B_in  = (const float*)d_in[4];
    const float* w_out = (const float*)d_in[5];
    const float* b_out = (const float*)d_in[6];
    const float* A_out = (const float*)d_in[7];
    const float* B_out = (const float*)d_in[8];
    float* out = (float*)d_out;

    __nv_bfloat16 *p_w1h, *p_w1l, *p_w2h, *p_w2l, *p_xh, *p_xl, *p_ah, *p_al;
    float *p_c;
    cudaGetSymbolAddress((void**)&p_w1h, g_w1h);
    cudaGetSymbolAddress((void**)&p_w1l, g_w1l);
    cudaGetSymbolAddress((void**)&p_w2h, g_w2h);
    cudaGetSymbolAddress((void**)&p_w2l, g_w2l);
    cudaGetSymbolAddress((void**)&p_xh,  g_xh);
    cudaGetSymbolAddress((void**)&p_xl,  g_xl);
    cudaGetSymbolAddress((void**)&p_c,   g_c);
    cudaGetSymbolAddress((void**)&p_ah,  g_ah);
    cudaGetSymbolAddress((void**)&p_al,  g_al);

    const int smem1 = 3 * (2 * 128 * 64 + 2 * 128 * 64);   // 98304
    const int smem2 = 4 * (2 * 128 * 64 + 2 * 64 * 64);    // 98304
    const int smemF = 98304;                                // Q + 2K + 2V
    cudaFuncSetAttribute((const void*)gemm_tc<128, true>,
                         cudaFuncAttributeMaxDynamicSharedMemorySize, smem1);
    cudaFuncSetAttribute((const void*)gemm_tc<64, false>,
                         cudaFuncAttributeMaxDynamicSharedMemorySize, smem2);
    cudaFuncSetAttribute((const void*)flash_tc,
                         cudaFuncAttributeMaxDynamicSharedMemorySize, smemF);

    {
        dim3 blk(32, 8);
        dim3 gp(N3E / 32, Ee / 32, 2);
        prep_wt2<<<gp, blk>>>(w_in, A_in, B_in, p_w1h, p_w1l,
                              w_out, A_out, B_out, p_w2h, p_w2l);
        cvt_x<<<Mrows * Ee / 4 / 256, 256>>>((const float4*)x, p_xh, p_xl);
    }
    {
        dim3 grid(N3E / 128, Mrows / 128);
        gemm_tc<128, true><<<grid, 256, smem1>>>(p_xh, p_xl, p_w1h, p_w1l, b_in, p_c, N3E);
    }
    {
        dim3 blk(32, 8);
        dim3 gv(LLen / 32, 2 * Bb * Hh);
        vtrans<<<gv, blk>>>();
    }
    {
        dim3 grid(Bb * Hh, 40);   // 40 fine-grained work items per bh, heavy-first
        flash_tc<<<grid, 256, smemF>>>();
        merge_kv<<<dim3(12, Bb * Hh), 256>>>();
    }
    {
        dim3 grid(Ee / 64, Mrows / 128);
        gemm_tc<64, false><<<grid, 256, smem2>>>(p_ah, p_al, p_w2h, p_w2l, b_out, out, Ee);
    }
}

// round 14
// speedup vs baseline: 1.0358x; 1.0358x over previous
#include <cuda_runtime.h>
#include <cuda_bf16.h>
#include <cstdint>
#include <math.h>

#define Hh 12
#define Ee 768
#define Dd 64
#define LLen 2048
#define Bb 2
#define Mrows (Bb*LLen)      // 4096
#define N3E (3*Ee)           // 2304
#define LORA 8.0f
#define LOG2E 1.44269504088896340736f

// ---------------- scratch ----------------
__device__ __nv_bfloat16 g_w1h[N3E * Ee], g_w1l[N3E * Ee];
__device__ __nv_bfloat16 g_w2h[Ee * Ee],  g_w2l[Ee * Ee];
__device__ __nv_bfloat16 g_xh [Mrows * Ee], g_xl [Mrows * Ee];
__device__ float g_c [Mrows * N3E];                  // qkv; q-region pre-scaled by log2e, tf32-rounded
__device__ float g_vt[Bb * Hh * Dd * LLen];          // V transposed: [bh*64+d][token]
__device__ __nv_bfloat16 g_ah [Mrows * Ee], g_al [Mrows * Ee];
// split-KV partials: 24 bh x 8 split-qt x 2 chunks
__device__ float g_po[384 * 128 * 64];
__device__ float g_pm[384 * 128];
__device__ float g_pl[384 * 128];

// slot schedule (size-descending): qt per slot; ch: 0/1 = split chunk, 2 = unsplit
__device__ const int d_qt[24] = {15,15,7,14,14,6,13,13,5,12,12,11,11,4,10,10,9,9,8,8,3,2,1,0};
__device__ const int d_ch[24] = { 0, 1,2, 0, 1,2, 0, 1,2, 0, 1, 0, 1,2, 0, 1,0,1,0,1,2,2,2,2};

// =================== helpers ===================
__device__ __forceinline__ uint32_t smem_u32(const void* p) {
    uint32_t a;
    asm("{ .reg .u64 t; cvta.to.shared.u64 t, %1; cvt.u32.u64 %0, t; }" : "=r"(a) : "l"(p));
    return a;
}
__device__ __forceinline__ float rna(float x) {
    uint32_t r;
    asm("cvt.rna.tf32.f32 %0, %1;" : "=r"(r) : "f"(x));
    return __uint_as_float(r);
}
__device__ __forceinline__ float ex2(float x) {
    float r;
    asm("ex2.approx.f32 %0, %1;" : "=f"(r) : "f"(x));
    return r;
}
__device__ __forceinline__ void cp16(uint32_t dst, const void* src) {
    asm volatile("cp.async.cg.shared.global [%0], [%1], 16;" :: "r"(dst), "l"(src));
}
#define CP_COMMIT() asm volatile("cp.async.commit_group;" ::: "memory")

__device__ __forceinline__ void ldsm4(uint32_t& r0, uint32_t& r1, uint32_t& r2, uint32_t& r3,
                                      uint32_t addr) {
    asm volatile("ldmatrix.sync.aligned.m8n8.x4.shared.b16 {%0,%1,%2,%3}, [%4];"
                 : "=r"(r0), "=r"(r1), "=r"(r2), "=r"(r3) : "r"(addr));
}
__device__ __forceinline__ void mma_tf32(float* c, uint32_t a0, uint32_t a1, uint32_t a2,
                                         uint32_t a3, uint32_t b0, uint32_t b1) {
    asm volatile("mma.sync.aligned.m16n8k8.row.col.f32.tf32.tf32.f32 "
                 "{%0,%1,%2,%3}, {%4,%5,%6,%7}, {%8,%9}, {%0,%1,%2,%3};"
                 : "+f"(c[0]), "+f"(c[1]), "+f"(c[2]), "+f"(c[3])
                 : "r"(a0), "r"(a1), "r"(a2), "r"(a3), "r"(b0), "r"(b1));
}
__device__ __forceinline__ void mma_bf16(float* c, uint32_t a0, uint32_t a1, uint32_t a2,
                                         uint32_t a3, uint32_t b0, uint32_t b1) {
    asm volatile("mma.sync.aligned.m16n8k16.row.col.f32.bf16.bf16.f32 "
                 "{%0,%1,%2,%3}, {%4,%5,%6,%7}, {%8,%9}, {%0,%1,%2,%3};"
                 : "+f"(c[0]), "+f"(c[1]), "+f"(c[2]), "+f"(c[3])
                 : "r"(a0), "r"(a1), "r"(a2), "r"(a3), "r"(b0), "r"(b1));
}
__device__ __forceinline__ void bf16_split(float f, __nv_bfloat16& h, __nv_bfloat16& l) {
    h = __float2bfloat16(f);
    l = __float2bfloat16(f - __bfloat162float(h));
}

// ---------------- prep (merged): wt = (w + 8*B@A)^T split into bf16 hi/lo ----------------
__global__ void prep_wt2(const float* __restrict__ w1, const float* __restrict__ A1,
                         const float* __restrict__ B1, __nv_bfloat16* __restrict__ w1h,
                         __nv_bfloat16* __restrict__ w1l,
                         const float* __restrict__ w2, const float* __restrict__ A2,
                         const float* __restrict__ B2, __nv_bfloat16* __restrict__ w2h,
                         __nv_bfloat16* __restrict__ w2l)
{
    const int z = blockIdx.z;
    const float* w  = z ? w2 : w1;
    const float* Aa = z ? A2 : A1;
    const float* Bm = z ? B2 : B1;
    __nv_bfloat16* wh = z ? w2h : w1h;
    __nv_bfloat16* wl = z ? w2l : w1l;
    const int ncols = z ? Ee : N3E;

    __shared__ float t[32][33];
    int o0 = blockIdx.x * 32, e0 = blockIdx.y * 32;
    if (o0 >= ncols) return;
    int tx = threadIdx.x, ty = threadIdx.y;
    #pragma unroll
    for (int r = 0; r < 4; r++) {
        int e = e0 + ty + r * 8, o = o0 + tx;
        float s = 0.f;
        #pragma unroll
        for (int q = 0; q < 4; q++) s += Bm[e*4 + q] * Aa[q*ncols + o];
        t[ty + r*8][tx] = w[(size_t)e * ncols + o] + LORA * s;
    }
    __syncthreads();
    #pragma unroll
    for (int r = 0; r < 4; r++) {
        int o = o0 + ty + r * 8, e = e0 + tx;
        __nv_bfloat16 hh, ll;
        bf16_split(t[tx][ty + r*8], hh, ll);
        wh[(size_t)o * Ee + e] = hh;
        wl[(size_t)o * Ee + e] = ll;
    }
}

// ---------------- x -> bf16 hi/lo split ----------------
__global__ void cvt_x(const float4* __restrict__ in, __nv_bfloat16* __restrict__ oh,
                      __nv_bfloat16* __restrict__ ol)
{
    int i = blockIdx.x * blockDim.x + threadIdx.x;
    float4 v = in[i];
    __nv_bfloat16 h0,l0,h1,l1,h2,l2,h3,l3;
    bf16_split(v.x, h0, l0); bf16_split(v.y, h1, l1);
    bf16_split(v.z, h2, l2); bf16_split(v.w, h3, l3);
    int o = i * 4;
    *(__nv_bfloat162*)&oh[o]     = __nv_bfloat162(h0, h1);
    *(__nv_bfloat162*)&oh[o + 2] = __nv_bfloat162(h2, h3);
    *(__nv_bfloat162*)&ol[o]     = __nv_bfloat162(l0, l1);
    *(__nv_bfloat162*)&ol[o + 2] = __nv_bfloat162(l2, l3);
}

// ---------------- V transpose: g_c v-region -> g_vt[bh*64+d][token] ----------------
__global__ void vtrans()
{
    __shared__ float t[32][33];
    const int bh   = blockIdx.y >> 1;
    const int dblk = (blockIdx.y & 1) * 32;
    const int tok0 = blockIdx.x * 32;
    const int b = bh / Hh, h = bh - b * Hh;
    const int tx = threadIdx.x, ty = threadIdx.y;
    const float* src = g_c + (size_t)(b * LLen) * N3E + 2 * Ee + h * Dd;
    #pragma unroll
    for (int r = 0; r < 4; r++) {
        int token = tok0 + ty + r * 8;
        t[ty + r*8][tx] = src[(size_t)token * N3E + dblk + tx];
    }
    __syncthreads();
    #pragma unroll
    for (int r = 0; r < 4; r++) {
        int d = dblk + ty + r * 8;
        g_vt[(size_t)(bh * Dd + d) * LLen + tok0 + tx] = t[tx][ty + r*8];
    }
}

// ---------------- bf16x2 mma.sync GEMM: C = A*Wt^T + bias (3-product split-2) ----------------
#define NTk 24   // 768/32

template<int TN, bool RNA>
__global__ void __launch_bounds__(256, 2)
gemm_tc(const __nv_bfloat16* __restrict__ Ah, const __nv_bfloat16* __restrict__ Al,
        const __nv_bfloat16* __restrict__ Wh, const __nv_bfloat16* __restrict__ Wl,
        const float* __restrict__ bias, float* __restrict__ C, int N)
{
    constexpr int MT = (TN == 128) ? 4 : 2;
    constexpr int WM = 128 / (MT * 16);
    constexpr int ABY = 128 * 64;
    constexpr int BBY = TN * 64;
    constexpr int SBYTES = 2 * ABY + 2 * BBY;
    constexpr int STG = (TN == 128) ? 3 : 4;

    extern __shared__ float sm[];
    const uint32_t sbase = smem_u32(sm);

    const int tid  = threadIdx.x;
    const int wid  = tid >> 5;
    const int lane = tid & 31;
    const int m0 = blockIdx.y * 128;
    const int n0 = blockIdx.x * TN;
    const int wm = wid & (WM - 1);
    const int wn = wid / WM;

    auto load_tile = [&](int kt) {
        const int st = kt % STG;
        const uint32_t sAh = sbase + st * SBYTES;
        const uint32_t sAl = sAh + ABY;
        const uint32_t sBh = sAl + ABY;
        const uint32_t sBl = sBh + BBY;
        const __nv_bfloat16* Agh = Ah + (size_t)m0 * Ee + kt * 32;
        const __nv_bfloat16* Agl = Al + (size_t)m0 * Ee + kt * 32;
        const __nv_bfloat16* Bgh = Wh + (size_t)n0 * Ee + kt * 32;
        const __nv_bfloat16* Bgl = Wl + (size_t)n0 * Ee + kt * 32;
        #pragma unroll
        for (int i = 0; i < 2; i++) {
            int f = tid + i * 256;
            int row = f >> 2, ch = f & 3;
            uint32_t off = row * 64 + ((ch ^ ((row >> 1) & 3)) << 4);
            cp16(sAh + off, Agh + (size_t)row * Ee + ch * 8);
            cp16(sAl + off, Agl + (size_t)row * Ee + ch * 8);
        }
        #pragma unroll
        for (int i = 0; i < TN / 64; i++) {
            int f = tid + i * 256;
            int row = f >> 2, ch = f & 3;
            uint32_t off = row * 64 + ((ch ^ ((row >> 1) & 3)) << 4);
            cp16(sBh + off, Bgh + (size_t)row * Ee + ch * 8);
            cp16(sBl + off, Bgl + (size_t)row * Ee + ch * 8);
        }
        CP_COMMIT();
    };

    float acc[MT][4][4];
    #pragma unroll
    for (int i = 0; i < MT; i++)
        #pragma unroll
        for (int j = 0; j < 4; j++)
            #pragma unroll
            for (int k = 0; k < 4; k++) acc[i][j][k] = 0.f;

    int arow[MT], bro[2];
    #pragma unroll
    for (int mt = 0; mt < MT; mt++) arow[mt] = wm * MT * 16 + mt * 16 + (lane & 15);
    const int achk = (lane >> 4) & 1;
    #pragma unroll
    for (int p = 0; p < 2; p++) bro[p] = wn * 32 + p * 16 + (lane & 7) + ((lane >> 4) & 1) * 8;
    const int bchk = (lane >> 3) & 1;

    #pragma unroll
    for (int kt = 0; kt < STG - 1; kt++) load_tile(kt);

    for (int it = 0; it < NTk; ++it) {
        const int st = it % STG;
        if (STG == 3) {
            if (it < NTk - 1) asm volatile("cp.async.wait_group 1;" ::: "memory");
            else              asm volatile("cp.async.wait_group 0;" ::: "memory");
        } else {
            if (it < NTk - 2)       asm volatile("cp.async.wait_group 2;" ::: "memory");
            else if (it == NTk - 2) asm volatile("cp.async.wait_group 1;" ::: "memory");
            else                    asm volatile("cp.async.wait_group 0;" ::: "memory");
        }
        __syncthreads();

        if (it + STG - 1 < NTk) load_tile(it + STG - 1);

        const uint32_t sAh = sbase + st * SBYTES;
        const uint32_t sAl = sAh + ABY;
        const uint32_t sBh = sAl + ABY;
        const uint32_t sBl = sBh + BBY;

        #pragma unroll
        for (int ks = 0; ks < 2; ks++) {
            uint32_t afh[MT][4];
            #pragma unroll
            for (int mt = 0; mt < MT; mt++)
                ldsm4(afh[mt][0], afh[mt][1], afh[mt][2], afh[mt][3],
                      sAh + arow[mt] * 64 + (((2*ks + achk) ^ ((arow[mt] >> 1) & 3)) << 4));
            uint32_t bfh[4][2];
            #pragma unroll
            for (int p = 0; p < 2; p++)
                ldsm4(bfh[2*p][0], bfh[2*p][1], bfh[2*p+1][0], bfh[2*p+1][1],
                      sBh + bro[p] * 64 + (((2*ks + bchk) ^ ((bro[p] >> 1) & 3)) << 4));
            #pragma unroll
            for (int mt = 0; mt < MT; mt++)
                #pragma unroll
                for (int nt = 0; nt < 4; nt++)
                    mma_bf16(acc[mt][nt], afh[mt][0], afh[mt][1], afh[mt][2], afh[mt][3],
                             bfh[nt][0], bfh[nt][1]);
            uint32_t bfl[4][2];
            #pragma unroll
            for (int p = 0; p < 2; p++)
                ldsm4(bfl[2*p][0], bfl[2*p][1], bfl[2*p+1][0], bfl[2*p+1][1],
                      sBl + bro[p] * 64 + (((2*ks + bchk) ^ ((bro[p] >> 1) & 3)) << 4));
            #pragma unroll
            for (int mt = 0; mt < MT; mt++)
                #pragma unroll
                for (int nt = 0; nt < 4; nt++)
                    mma_bf16(acc[mt][nt], afh[mt][0], afh[mt][1], afh[mt][2], afh[mt][3],
                             bfl[nt][0], bfl[nt][1]);
            uint32_t afl[MT][4];
            #pragma unroll
            for (int mt = 0; mt < MT; mt++)
                ldsm4(afl[mt][0], afl[mt][1], afl[mt][2], afl[mt][3],
                      sAl + arow[mt] * 64 + (((2*ks + achk) ^ ((arow[mt] >> 1) & 3)) << 4));
            #pragma unroll
            for (int mt = 0; mt < MT; mt++)
                #pragma unroll
                for (int nt = 0; nt < 4; nt++)
                    mma_bf16(acc[mt][nt], afl[mt][0], afl[mt][1], afl[mt][2], afl[mt][3],
                             bfh[nt][0], bfh[nt][1]);
        }
    }

    const int g = lane >> 2, t = lane & 3;
    // q-region of GEMM1 gets log2e folded in (softmax runs in log2 domain)
    const float qs = (RNA && n0 < Ee) ? LOG2E : 1.f;
    #pragma unroll
    for (int nt = 0; nt < 4; nt++) {
        const int col = n0 + wn * 32 + nt * 8 + 2 * t;
        float2 bz = *(const float2*)&bias[col];
        #pragma unroll
        for (int mt = 0; mt < MT; mt++) {
            const int r0 = m0 + wm * MT * 16 + mt * 16 + g;
            float2 v0, v1;
            if (RNA) {
                v0.x = rna(qs * (acc[mt][nt][0] + bz.x)); v0.y = rna(qs * (acc[mt][nt][1] + bz.y));
                v1.x = rna(qs * (acc[mt][nt][2] + bz.x)); v1.y = rna(qs * (acc[mt][nt][3] + bz.y));
            } else {
                v0.x = acc[mt][nt][0] + bz.x; v0.y = acc[mt][nt][1] + bz.y;
                v1.x = acc[mt][nt][2] + bz.x; v1.y = acc[mt][nt][3] + bz.y;
            }
            *(float2*)&C[(size_t)r0 * N + col]       = v0;
            *(float2*)&C[(size_t)(r0 + 8) * N + col] = v1;
        }
    }
}

// ---------------- flash attention: tf32 mma.sync, causal, split-KV (round-12 schedule) ----------------
// v9: 24 slots/bh, 2-way split for qt>=8; softmax in log2 domain (ex2).
// smem: Q 32KB @0 | K[2] 16KB @32K,48K | V[2] 16KB @64K,80K  = 96KB
__global__ void __launch_bounds__(256, 2)
flash_tc()
{
    extern __shared__ float smf[];
    const uint32_t QsB = smem_u32(smf);

    const int tid  = threadIdx.x;
    const int wid  = tid >> 5;
    const int lane = tid & 31;
    const int g = lane >> 2, t = lane & 3;

    const int slot = blockIdx.y;
    const int qt = d_qt[slot];
    const int ch = d_ch[slot];
    const int q0 = qt * 128;
    const bool split = (ch != 2);
    const int t0 = (split && ch == 1) ? (qt + 1) : 0;
    const int t1 = (split && ch == 0) ? (qt + 1) : (2 * qt + 2);

    const int bh = blockIdx.x;
    const int b  = bh / Hh;
    const int h  = bh - b * Hh;

    const float* qg = g_c + (size_t)(b * LLen) * N3E + h * Dd;
    const float* kg = qg + Ee;
    const float* vt = g_vt + (size_t)bh * Dd * LLen;

    const int srow = tid >> 4;
    const int sch  = tid & 15;

    auto load_kv = [&](int kb, int buf) {
        const uint32_t KsB = QsB + 32768u + (uint32_t)buf * 16384u;
        const uint32_t VtB = QsB + 65536u + (uint32_t)buf * 16384u;
        #pragma unroll
        for (int i = 0; i < 4; i++) {
            int r = srow + i * 16;
            cp16(KsB + r * 256 + ((sch ^ ((r & 7) << 1)) << 4),
                 kg + (size_t)(kb + r) * N3E + sch * 4);
        }
        #pragma unroll
        for (int i = 0; i < 4; i++) {
            int d = srow + i * 16;
            cp16(VtB + d * 256 + ((sch ^ ((d & 7) << 1)) << 4),
                 vt + (size_t)d * LLen + kb + sch * 4);
        }
        CP_COMMIT();
    };

    // Q (already log2e-scaled + tf32-rounded in gmem)
    #pragma unroll
    for (int i = 0; i < 8; i++) {
        int r = srow + i * 16;
        cp16(QsB + r * 256 + ((sch ^ ((r & 7) << 1)) << 4),
             qg + (size_t)(q0 + r) * N3E + sch * 4);
    }
    load_kv(t0 * 64, t0 & 1);

    float m[2] = {-INFINITY, -INFINITY};
    float l[2] = {0.f, 0.f};
    float oacc[8][4];
    #pragma unroll
    for (int j = 0; j < 8; j++)
        #pragma unroll
        for (int k = 0; k < 4; k++) oacc[j][k] = 0.f;

    const int arow = (wid << 4) + (lane & 15);
    const int achk = (lane >> 4) & 1;
    const int asw  = (arow & 7) << 1;
    int brow[4];
    #pragma unroll
    for (int p = 0; p < 4; p++) brow[p] = (p << 4) + (lane & 7) + (((lane >> 4) & 1) << 3);
    const int bchk = (lane >> 3) & 1;

    const int srcA = (lane & ~3) | (t >> 1);
    const int srcB = srcA + 2;
    const bool odd = (t & 1);

    for (int ti = t0; ti < t1; ti++) {
        const int kb = ti * 64;
        const int buf = ti & 1;
        const uint32_t KsB = QsB + 32768u + (uint32_t)buf * 16384u;
        const uint32_t VtB = QsB + 65536u + (uint32_t)buf * 16384u;

        asm volatile("cp.async.wait_group 0;" ::: "memory");
        __syncthreads();
        if (ti + 1 < t1) load_kv(kb + 64, buf ^ 1);

        // fully-masked warp in final diagonal tile: skip compute (identical result)
        if (q0 + (wid << 4) + 15 < kb) continue;

        // ---- S' = (log2e*Q) K^T ----
        float sacc[8][4];
        #pragma unroll
        for (int j = 0; j < 8; j++)
            #pragma unroll
            for (int k = 0; k < 4; k++) sacc[j][k] = 0.f;

        #pragma unroll
        for (int ks = 0; ks < 8; ks++) {
            uint32_t a0, a1, a2, a3;
            ldsm4(a0, a1, a2, a3,
                  QsB + arow * 256 + ((((ks << 1) + achk) ^ asw) << 4));
            uint32_t bf[8][2];
            #pragma unroll
            for (int p = 0; p < 4; p++)
                ldsm4(bf[2*p][0], bf[2*p][1], bf[2*p+1][0], bf[2*p+1][1],
                      KsB + brow[p] * 256 + ((((ks << 1) + bchk) ^ ((brow[p] & 7) << 1)) << 4));
            #pragma unroll
            for (int j = 0; j < 8; j++)
                mma_tf32(sacc[j], a0, a1, a2, a3, bf[j][0], bf[j][1]);
        }

        // causal mask (diagonal tiles)
        if (kb >= q0) {
            const int r0g = q0 + (wid << 4) + g;
            #pragma unroll
            for (int j = 0; j < 8; j++) {
                int cg = kb + (j << 3) + (t << 1);
                if (cg > r0g)         sacc[j][0] = -1e9f;
                if (cg + 1 > r0g)     sacc[j][1] = -1e9f;
                if (cg > r0g + 8)     sacc[j][2] = -1e9f;
                if (cg + 1 > r0g + 8) sacc[j][3] = -1e9f;
            }
        }

        // ---- online softmax in log2 domain (rows g and g+8) ----
        float mt0 = -INFINITY, mt1 = -INFINITY;
        #pragma unroll
        for (int j = 0; j < 8; j++) {
            mt0 = fmaxf(mt0, fmaxf(sacc[j][0], sacc[j][1]));
            mt1 = fmaxf(mt1, fmaxf(sacc[j][2], sacc[j][3]));
        }
        mt0 = fmaxf(mt0, __shfl_xor_sync(0xffffffffu, mt0, 1));
        mt0 = fmaxf(mt0, __shfl_xor_sync(0xffffffffu, mt0, 2));
        mt1 = fmaxf(mt1, __shfl_xor_sync(0xffffffffu, mt1, 1));
        mt1 = fmaxf(mt1, __shfl_xor_sync(0xffffffffu, mt1, 2));
        float mn0 = fmaxf(m[0], mt0), mn1 = fmaxf(m[1], mt1);
        float sc0 = ex2(m[0] - mn0), sc1 = ex2(m[1] - mn1);
        m[0] = mn0; m[1] = mn1;
        float ls0 = 0.f, ls1 = 0.f;
        #pragma unroll
        for (int j = 0; j < 8; j++) {
            sacc[j][0] = rna(ex2(sacc[j][0] - mn0)); ls0 += sacc[j][0];
            sacc[j][1] = rna(ex2(sacc[j][1] - mn0)); ls0 += sacc[j][1];
            sacc[j][2] = rna(ex2(sacc[j][2] - mn1)); ls1 += sacc[j][2];
            sacc[j][3] = rna(ex2(sacc[j][3] - mn1)); ls1 += sacc[j][3];
        }
        ls0 += __shfl_xor_sync(0xffffffffu, ls0, 1);
        ls0 += __shfl_xor_sync(0xffffffffu, ls0, 2);
        ls1 += __shfl_xor_sync(0xffffffffu, ls1, 1);
        ls1 += __shfl_xor_sync(0xffffffffu, ls1, 2);
        l[0] = l[0] * sc0 + ls0;
        l[1] = l[1] * sc1 + ls1;
        #pragma unroll
        for (int j = 0; j < 8; j++) {
            oacc[j][0] *= sc0; oacc[j][1] *= sc0;
            oacc[j][2] *= sc1; oacc[j][3] *= sc1;
        }

        // ---- O += P V : P C-frag -> A-frag via shuffles, then MMA ----
        #pragma unroll
        for (int ks = 0; ks < 8; ks++) {
            float v0 = __shfl_sync(0xffffffffu, sacc[ks][0], srcA);
            float v1 = __shfl_sync(0xffffffffu, sacc[ks][1], srcA);
            float v2 = __shfl_sync(0xffffffffu, sacc[ks][2], srcA);
            float v3 = __shfl_sync(0xffffffffu, sacc[ks][3], srcA);
            float w0 = __shfl_sync(0xffffffffu, sacc[ks][0], srcB);
            float w1 = __shfl_sync(0xffffffffu, sacc[ks][1], srcB);
            float w2 = __shfl_sync(0xffffffffu, sacc[ks][2], srcB);
            float w3 = __shfl_sync(0xffffffffu, sacc[ks][3], srcB);
            uint32_t pa0 = __float_as_uint(odd ? v1 : v0);
            uint32_t pa1 = __float_as_uint(odd ? v3 : v2);
            uint32_t pa2 = __float_as_uint(odd ? w1 : w0);
            uint32_t pa3 = __float_as_uint(odd ? w3 : w2);

            uint32_t vf[8][2];
            #pragma unroll
            for (int p = 0; p < 4; p++)
                ldsm4(vf[2*p][0], vf[2*p][1], vf[2*p+1][0], vf[2*p+1][1],
                      VtB + brow[p] * 256 + ((((ks << 1) + bchk) ^ ((brow[p] & 7) << 1)) << 4));
            #pragma unroll
            for (int j = 0; j < 8; j++)
                mma_tf32(oacc[j], pa0, pa1, pa2, pa3, vf[j][0], vf[j][1]);
        }
    }

    const int lr0 = (wid << 4) + g;
    const int lr1 = lr0 + 8;
    if (split) {
        // ---- store unnormalized partial ----
        const int pidx = (bh * 8 + (qt - 8)) * 2 + ch;
        float* po = g_po + (size_t)pidx * 128 * 64;
        #pragma unroll
        for (int j = 0; j < 8; j++) {
            int d = (j << 3) + (t << 1);
            *(float2*)&po[lr0 * 64 + d] = make_float2(oacc[j][0], oacc[j][1]);
            *(float2*)&po[lr1 * 64 + d] = make_float2(oacc[j][2], oacc[j][3]);
        }
        if (t == 0) {
            g_pm[pidx * 128 + lr0] = m[0]; g_pl[pidx * 128 + lr0] = l[0];
            g_pm[pidx * 128 + lr1] = m[1]; g_pl[pidx * 128 + lr1] = l[1];
        }
    } else {
        // ---- epilogue: normalize, split bf16 hi/lo, store ----
        const float inv0 = 1.f / l[0], inv1 = 1.f / l[1];
        const int grow = b * LLen + q0 + lr0;
        __nv_bfloat16* ah0 = g_ah + (size_t)grow * Ee + h * Dd;
        __nv_bfloat16* al0 = g_al + (size_t)grow * Ee + h * Dd;
        __nv_bfloat16* ah1 = ah0 + 8 * Ee;
        __nv_bfloat16* al1 = al0 + 8 * Ee;
        #pragma unroll
        for (int j = 0; j < 8; j++) {
            int d = (j << 3) + (t << 1);
            float o0 = oacc[j][0] * inv0, o1 = oacc[j][1] * inv0;
            float o2 = oacc[j][2] * inv1, o3 = oacc[j][3] * inv1;
            __nv_bfloat16 h0,l0b,h1,l1b,h2,l2b,h3,l3b;
            bf16_split(o0, h0, l0b); bf16_split(o1, h1, l1b);
            bf16_split(o2, h2, l2b); bf16_split(o3, h3, l3b);
            *(__nv_bfloat162*)&ah0[d] = __nv_bfloat162(h0, h1);
            *(__nv_bfloat162*)&al0[d] = __nv_bfloat162(l0b, l1b);
            *(__nv_bfloat162*)&ah1[d] = __nv_bfloat162(h2, h3);
            *(__nv_bfloat162*)&al1[d] = __nv_bfloat162(l2b, l3b);
        }
    }
}

// ---------------- merge split-KV partials (log2-domain m) ----------------
// grid (8, 24): x = qt-8, y = bh. 256 threads: row = tid/2, col half
__global__ void merge_kv()
{
    const int s  = blockIdx.x;
    const int bh = blockIdx.y;
    const int qt = 8 + s;
    const int b = bh / Hh, h = bh - b * Hh;
    const int p0 = (bh * 8 + s) * 2;
    const int p1 = p0 + 1;
    const int r  = threadIdx.x >> 1;
    const int c0 = (threadIdx.x & 1) * 32;

    float m1 = g_pm[p0 * 128 + r], l1 = g_pl[p0 * 128 + r];
    float m2 = g_pm[p1 * 128 + r], l2 = g_pl[p1 * 128 + r];
    float mm = fmaxf(m1, m2);
    float e1 = ex2(m1 - mm), e2 = ex2(m2 - mm);
    float inv = 1.f / (l1 * e1 + l2 * e2);

    const float* o1 = g_po + ((size_t)p0 * 128 + r) * 64 + c0;
    const float* o2 = g_po + ((size_t)p1 * 128 + r) * 64 + c0;
    const int grow = b * LLen + qt * 128 + r;
    __nv_bfloat16* ah = g_ah + (size_t)grow * Ee + h * Dd + c0;
    __nv_bfloat16* al = g_al + (size_t)grow * Ee + h * Dd + c0;

    #pragma unroll
    for (int c = 0; c < 32; c += 2) {
        float2 a = *(const float2*)&o1[c];
        float2 bx = *(const float2*)&o2[c];
        float v0 = (a.x * e1 + bx.x * e2) * inv;
        float v1 = (a.y * e1 + bx.y * e2) * inv;
        __nv_bfloat16 h0, l0, h1, l1b;
        bf16_split(v0, h0, l0); bf16_split(v1, h1, l1b);
        *(__nv_bfloat162*)&ah[c] = __nv_bfloat162(h0, h1);
        *(__nv_bfloat162*)&al[c] = __nv_bfloat162(l0, l1b);
    }
}

// ---------------- launch ----------------
extern "C" void kernel_launch(void* const* d_in, const int* in_sizes, int n_in,
                              void* d_out, int out_size)
{
    const float* x     = (const float*)d_in[0];
    const float* w_in  = (const float*)d_in[1];
    const float* b_in  = (const float*)d_in[2];
    const float* A_in  = (const float*)d_in[3];
    const float* B_in  = (const float*)d_in[4];
    const float* w_out = (const float*)d_in[5];
    const float* b_out = (const float*)d_in[6];
    const float* A_out = (const float*)d_in[7];
    const float* B_out = (const float*)d_in[8];
    float* out = (float*)d_out;

    __nv_bfloat16 *p_w1h, *p_w1l, *p_w2h, *p_w2l, *p_xh, *p_xl, *p_ah, *p_al;
    float *p_c;
    cudaGetSymbolAddress((void**)&p_w1h, g_w1h);
    cudaGetSymbolAddress((void**)&p_w1l, g_w1l);
    cudaGetSymbolAddress((void**)&p_w2h, g_w2h);
    cudaGetSymbolAddress((void**)&p_w2l, g_w2l);
    cudaGetSymbolAddress((void**)&p_xh,  g_xh);
    cudaGetSymbolAddress((void**)&p_xl,  g_xl);
    cudaGetSymbolAddress((void**)&p_c,   g_c);
    cudaGetSymbolAddress((void**)&p_ah,  g_ah);
    cudaGetSymbolAddress((void**)&p_al,  g_al);

    const int smem1 = 3 * (2 * 128 * 64 + 2 * 128 * 64);   // 98304
    const int smem2 = 4 * (2 * 128 * 64 + 2 * 64 * 64);    // 98304
    const int smemF = 98304;                                // Q + 2K + 2V
    cudaFuncSetAttribute((const void*)gemm_tc<128, true>,
                         cudaFuncAttributeMaxDynamicSharedMemorySize, smem1);
    cudaFuncSetAttribute((const void*)gemm_tc<64, false>,
                         cudaFuncAttributeMaxDynamicSharedMemorySize, smem2);
    cudaFuncSetAttribute((const void*)flash_tc,
                         cudaFuncAttributeMaxDynamicSharedMemorySize, smemF);

    {
        dim3 blk(32, 8);
        dim3 gp(N3E / 32, Ee / 32, 2);
        prep_wt2<<<gp, blk>>>(w_in, A_in, B_in, p_w1h, p_w1l,
                              w_out, A_out, B_out, p_w2h, p_w2l);
        cvt_x<<<Mrows * Ee / 4 / 256, 256>>>((const float4*)x, p_xh, p_xl);
    }
    {
        dim3 grid(N3E / 128, Mrows / 128);
        gemm_tc<128, true><<<grid, 256, smem1>>>(p_xh, p_xl, p_w1h, p_w1l, b_in, p_c, N3E);
    }
    {
        dim3 blk(32, 8);
        dim3 gv(LLen / 32, 2 * Bb * Hh);
        vtrans<<<gv, blk>>>();
    }
    {
        dim3 grid(Bb * Hh, 24);   // round-12 schedule: 2-way split for qt>=8
        flash_tc<<<grid, 256, smemF>>>();
        merge_kv<<<dim3(8, Bb * Hh), 256>>>();
    }
    {
        dim3 grid(Ee / 64, Mrows / 128);
        gemm_tc<64, false><<<grid, 256, smem2>>>(p_ah, p_al, p_w2h, p_w2l, b_out, out, Ee);
    }
}

// round 15
// speedup vs baseline: 1.0488x; 1.0125x over previous
#include <cuda_runtime.h>
#include <cuda_bf16.h>
#include <cstdint>
#include <math.h>

#define Hh 12
#define Ee 768
#define Dd 64
#define LLen 2048
#define Bb 2
#define Mrows (Bb*LLen)      // 4096
#define N3E (3*Ee)           // 2304
#define LORA 8.0f

// ---------------- scratch ----------------
__device__ __nv_bfloat16 g_w1h[N3E * Ee], g_w1l[N3E * Ee];
__device__ __nv_bfloat16 g_w2h[Ee * Ee],  g_w2l[Ee * Ee];
__device__ __nv_bfloat16 g_xh [Mrows * Ee], g_xl [Mrows * Ee];
__device__ float g_c [Mrows * N3E];                  // qkv, tf32-rounded at GEMM1 epilogue
__device__ float g_vt[Bb * Hh * Dd * LLen];          // V transposed: [bh*64+d][token]
__device__ __nv_bfloat16 g_ah [Mrows * Ee], g_al [Mrows * Ee];
// split-KV partials: 24 bh x 8 split-qt x 2 chunks
__device__ float g_po[384 * 128 * 64];
__device__ float g_pm[384 * 128];
__device__ float g_pl[384 * 128];

// slot schedule (size-descending): qt per slot; ch: 0/1 = split chunk, 2 = unsplit
__device__ const int d_qt[24] = {15,15,7,14,14,6,13,13,5,12,12,11,11,4,10,10,9,9,8,8,3,2,1,0};
__device__ const int d_ch[24] = { 0, 1,2, 0, 1,2, 0, 1,2, 0, 1, 0, 1,2, 0, 1,0,1,0,1,2,2,2,2};

// =================== helpers ===================
__device__ __forceinline__ uint32_t smem_u32(const void* p) {
    uint32_t a;
    asm("{ .reg .u64 t; cvta.to.shared.u64 t, %1; cvt.u32.u64 %0, t; }" : "=r"(a) : "l"(p));
    return a;
}
__device__ __forceinline__ float rna(float x) {
    uint32_t r;
    asm("cvt.rna.tf32.f32 %0, %1;" : "=r"(r) : "f"(x));
    return __uint_as_float(r);
}
__device__ __forceinline__ void cp16(uint32_t dst, const void* src) {
    asm volatile("cp.async.cg.shared.global [%0], [%1], 16;" :: "r"(dst), "l"(src));
}
#define CP_COMMIT() asm volatile("cp.async.commit_group;" ::: "memory")

__device__ __forceinline__ void ldsm4(uint32_t& r0, uint32_t& r1, uint32_t& r2, uint32_t& r3,
                                      uint32_t addr) {
    asm volatile("ldmatrix.sync.aligned.m8n8.x4.shared.b16 {%0,%1,%2,%3}, [%4];"
                 : "=r"(r0), "=r"(r1), "=r"(r2), "=r"(r3) : "r"(addr));
}
__device__ __forceinline__ void mma_tf32(float* c, uint32_t a0, uint32_t a1, uint32_t a2,
                                         uint32_t a3, uint32_t b0, uint32_t b1) {
    asm volatile("mma.sync.aligned.m16n8k8.row.col.f32.tf32.tf32.f32 "
                 "{%0,%1,%2,%3}, {%4,%5,%6,%7}, {%8,%9}, {%0,%1,%2,%3};"
                 : "+f"(c[0]), "+f"(c[1]), "+f"(c[2]), "+f"(c[3])
                 : "r"(a0), "r"(a1), "r"(a2), "r"(a3), "r"(b0), "r"(b1));
}
__device__ __forceinline__ void mma_bf16(float* c, uint32_t a0, uint32_t a1, uint32_t a2,
                                         uint32_t a3, uint32_t b0, uint32_t b1) {
    asm volatile("mma.sync.aligned.m16n8k16.row.col.f32.bf16.bf16.f32 "
                 "{%0,%1,%2,%3}, {%4,%5,%6,%7}, {%8,%9}, {%0,%1,%2,%3};"
                 : "+f"(c[0]), "+f"(c[1]), "+f"(c[2]), "+f"(c[3])
                 : "r"(a0), "r"(a1), "r"(a2), "r"(a3), "r"(b0), "r"(b1));
}
__device__ __forceinline__ void bf16_split(float f, __nv_bfloat16& h, __nv_bfloat16& l) {
    h = __float2bfloat16(f);
    l = __float2bfloat16(f - __bfloat162float(h));
}

// ---------------- prep (merged): wt = (w + 8*B@A)^T split into bf16 hi/lo ----------------
__global__ void prep_wt2(const float* __restrict__ w1, const float* __restrict__ A1,
                         const float* __restrict__ B1, __nv_bfloat16* __restrict__ w1h,
                         __nv_bfloat16* __restrict__ w1l,
                         const float* __restrict__ w2, const float* __restrict__ A2,
                         const float* __restrict__ B2, __nv_bfloat16* __restrict__ w2h,
                         __nv_bfloat16* __restrict__ w2l)
{
    const int z = blockIdx.z;
    const float* w  = z ? w2 : w1;
    const float* Aa = z ? A2 : A1;
    const float* Bm = z ? B2 : B1;
    __nv_bfloat16* wh = z ? w2h : w1h;
    __nv_bfloat16* wl = z ? w2l : w1l;
    const int ncols = z ? Ee : N3E;

    __shared__ float t[32][33];
    int o0 = blockIdx.x * 32, e0 = blockIdx.y * 32;
    if (o0 >= ncols) return;
    int tx = threadIdx.x, ty = threadIdx.y;
    #pragma unroll
    for (int r = 0; r < 4; r++) {
        int e = e0 + ty + r * 8, o = o0 + tx;
        float s = 0.f;
        #pragma unroll
        for (int q = 0; q < 4; q++) s += Bm[e*4 + q] * Aa[q*ncols + o];
        t[ty + r*8][tx] = w[(size_t)e * ncols + o] + LORA * s;
    }
    __syncthreads();
    #pragma unroll
    for (int r = 0; r < 4; r++) {
        int o = o0 + ty + r * 8, e = e0 + tx;
        __nv_bfloat16 hh, ll;
        bf16_split(t[tx][ty + r*8], hh, ll);
        wh[(size_t)o * Ee + e] = hh;
        wl[(size_t)o * Ee + e] = ll;
    }
}

// ---------------- x -> bf16 hi/lo split ----------------
__global__ void cvt_x(const float4* __restrict__ in, __nv_bfloat16* __restrict__ oh,
                      __nv_bfloat16* __restrict__ ol)
{
    int i = blockIdx.x * blockDim.x + threadIdx.x;
    float4 v = in[i];
    __nv_bfloat16 h0,l0,h1,l1,h2,l2,h3,l3;
    bf16_split(v.x, h0, l0); bf16_split(v.y, h1, l1);
    bf16_split(v.z, h2, l2); bf16_split(v.w, h3, l3);
    int o = i * 4;
    *(__nv_bfloat162*)&oh[o]     = __nv_bfloat162(h0, h1);
    *(__nv_bfloat162*)&oh[o + 2] = __nv_bfloat162(h2, h3);
    *(__nv_bfloat162*)&ol[o]     = __nv_bfloat162(l0, l1);
    *(__nv_bfloat162*)&ol[o + 2] = __nv_bfloat162(l2, l3);
}

// ---------------- V transpose: g_c v-region -> g_vt[bh*64+d][token] ----------------
__global__ void vtrans()
{
    __shared__ float t[32][33];
    const int bh   = blockIdx.y >> 1;
    const int dblk = (blockIdx.y & 1) * 32;
    const int tok0 = blockIdx.x * 32;
    const int b = bh / Hh, h = bh - b * Hh;
    const int tx = threadIdx.x, ty = threadIdx.y;
    const float* src = g_c + (size_t)(b * LLen) * N3E + 2 * Ee + h * Dd;
    #pragma unroll
    for (int r = 0; r < 4; r++) {
        int token = tok0 + ty + r * 8;
        t[ty + r*8][tx] = src[(size_t)token * N3E + dblk + tx];
    }
    __syncthreads();
    #pragma unroll
    for (int r = 0; r < 4; r++) {
        int d = dblk + ty + r * 8;
        g_vt[(size_t)(bh * Dd + d) * LLen + tok0 + tx] = t[tx][ty + r*8];
    }
}

// ---------------- bf16x2 mma.sync GEMM1: 128x128 tile (round-12 form) ----------------
#define NTk 24   // 768/32

__global__ void __launch_bounds__(256, 2)
gemm_tc1(const __nv_bfloat16* __restrict__ Ah, const __nv_bfloat16* __restrict__ Al,
         const __nv_bfloat16* __restrict__ Wh, const __nv_bfloat16* __restrict__ Wl,
         const float* __restrict__ bias, float* __restrict__ C, int N)
{
    constexpr int MT = 4;
    constexpr int ABY = 128 * 64;
    constexpr int BBY = 128 * 64;
    constexpr int SBYTES = 2 * ABY + 2 * BBY;
    constexpr int STG = 3;

    extern __shared__ float sm[];
    const uint32_t sbase = smem_u32(sm);

    const int tid  = threadIdx.x;
    const int wid  = tid >> 5;
    const int lane = tid & 31;
    const int m0 = blockIdx.y * 128;
    const int n0 = blockIdx.x * 128;
    const int wm = wid & 1;
    const int wn = wid >> 1;

    auto load_tile = [&](int kt) {
        const int st = kt % STG;
        const uint32_t sAh = sbase + st * SBYTES;
        const uint32_t sAl = sAh + ABY;
        const uint32_t sBh = sAl + ABY;
        const uint32_t sBl = sBh + BBY;
        const __nv_bfloat16* Agh = Ah + (size_t)m0 * Ee + kt * 32;
        const __nv_bfloat16* Agl = Al + (size_t)m0 * Ee + kt * 32;
        const __nv_bfloat16* Bgh = Wh + (size_t)n0 * Ee + kt * 32;
        const __nv_bfloat16* Bgl = Wl + (size_t)n0 * Ee + kt * 32;
        #pragma unroll
        for (int i = 0; i < 2; i++) {
            int f = tid + i * 256;
            int row = f >> 2, ch = f & 3;
            uint32_t off = row * 64 + ((ch ^ ((row >> 1) & 3)) << 4);
            cp16(sAh + off, Agh + (size_t)row * Ee + ch * 8);
            cp16(sAl + off, Agl + (size_t)row * Ee + ch * 8);
            cp16(sBh + off, Bgh + (size_t)row * Ee + ch * 8);
            cp16(sBl + off, Bgl + (size_t)row * Ee + ch * 8);
        }
        CP_COMMIT();
    };

    float acc[MT][4][4];
    #pragma unroll
    for (int i = 0; i < MT; i++)
        #pragma unroll
        for (int j = 0; j < 4; j++)
            #pragma unroll
            for (int k = 0; k < 4; k++) acc[i][j][k] = 0.f;

    int arow[MT], bro[2];
    #pragma unroll
    for (int mt = 0; mt < MT; mt++) arow[mt] = wm * MT * 16 + mt * 16 + (lane & 15);
    const int achk = (lane >> 4) & 1;
    #pragma unroll
    for (int p = 0; p < 2; p++) bro[p] = wn * 32 + p * 16 + (lane & 7) + ((lane >> 4) & 1) * 8;
    const int bchk = (lane >> 3) & 1;

    #pragma unroll
    for (int kt = 0; kt < STG - 1; kt++) load_tile(kt);

    for (int it = 0; it < NTk; ++it) {
        const int st = it % STG;
        if (it < NTk - 1) asm volatile("cp.async.wait_group 1;" ::: "memory");
        else              asm volatile("cp.async.wait_group 0;" ::: "memory");
        __syncthreads();

        if (it + STG - 1 < NTk) load_tile(it + STG - 1);

        const uint32_t sAh = sbase + st * SBYTES;
        const uint32_t sAl = sAh + ABY;
        const uint32_t sBh = sAl + ABY;
        const uint32_t sBl = sBh + BBY;

        #pragma unroll
        for (int ks = 0; ks < 2; ks++) {
            uint32_t afh[MT][4];
            #pragma unroll
            for (int mt = 0; mt < MT; mt++)
                ldsm4(afh[mt][0], afh[mt][1], afh[mt][2], afh[mt][3],
                      sAh + arow[mt] * 64 + (((2*ks + achk) ^ ((arow[mt] >> 1) & 3)) << 4));
            uint32_t bfh[4][2];
            #pragma unroll
            for (int p = 0; p < 2; p++)
                ldsm4(bfh[2*p][0], bfh[2*p][1], bfh[2*p+1][0], bfh[2*p+1][1],
                      sBh + bro[p] * 64 + (((2*ks + bchk) ^ ((bro[p] >> 1) & 3)) << 4));
            #pragma unroll
            for (int mt = 0; mt < MT; mt++)
                #pragma unroll
                for (int nt = 0; nt < 4; nt++)
                    mma_bf16(acc[mt][nt], afh[mt][0], afh[mt][1], afh[mt][2], afh[mt][3],
                             bfh[nt][0], bfh[nt][1]);
            uint32_t bfl[4][2];
            #pragma unroll
            for (int p = 0; p < 2; p++)
                ldsm4(bfl[2*p][0], bfl[2*p][1], bfl[2*p+1][0], bfl[2*p+1][1],
                      sBl + bro[p] * 64 + (((2*ks + bchk) ^ ((bro[p] >> 1) & 3)) << 4));
            #pragma unroll
            for (int mt = 0; mt < MT; mt++)
                #pragma unroll
                for (int nt = 0; nt < 4; nt++)
                    mma_bf16(acc[mt][nt], afh[mt][0], afh[mt][1], afh[mt][2], afh[mt][3],
                             bfl[nt][0], bfl[nt][1]);
            uint32_t afl[MT][4];
            #pragma unroll
            for (int mt = 0; mt < MT; mt++)
                ldsm4(afl[mt][0], afl[mt][1], afl[mt][2], afl[mt][3],
                      sAl + arow[mt] * 64 + (((2*ks + achk) ^ ((arow[mt] >> 1) & 3)) << 4));
            #pragma unroll
            for (int mt = 0; mt < MT; mt++)
                #pragma unroll
                for (int nt = 0; nt < 4; nt++)
                    mma_bf16(acc[mt][nt], afl[mt][0], afl[mt][1], afl[mt][2], afl[mt][3],
                             bfh[nt][0], bfh[nt][1]);
        }
    }

    const int g = lane >> 2, t = lane & 3;
    #pragma unroll
    for (int nt = 0; nt < 4; nt++) {
        const int col = n0 + wn * 32 + nt * 8 + 2 * t;
        float2 bz = *(const float2*)&bias[col];
        #pragma unroll
        for (int mt = 0; mt < MT; mt++) {
            const int r0 = m0 + wm * MT * 16 + mt * 16 + g;
            float2 v0, v1;
            v0.x = rna(acc[mt][nt][0] + bz.x); v0.y = rna(acc[mt][nt][1] + bz.y);
            v1.x = rna(acc[mt][nt][2] + bz.x); v1.y = rna(acc[mt][nt][3] + bz.y);
            *(float2*)&C[(size_t)r0 * N + col]       = v0;
            *(float2*)&C[(size_t)(r0 + 8) * N + col] = v1;
        }
    }
}

// ---------------- bf16x2 mma.sync GEMM2: 64x64 tile (better wave balance) ----------------
__global__ void __launch_bounds__(256, 2)
gemm_tc2(const __nv_bfloat16* __restrict__ Ah, const __nv_bfloat16* __restrict__ Al,
         const __nv_bfloat16* __restrict__ Wh, const __nv_bfloat16* __restrict__ Wl,
         const float* __restrict__ bias, float* __restrict__ C, int N)
{
    constexpr int ABY = 64 * 64;            // 4096 bytes per split
    constexpr int SBYTES = 4 * ABY;         // 16384/stage
    constexpr int STG = 4;

    extern __shared__ float sm[];
    const uint32_t sbase = smem_u32(sm);

    const int tid  = threadIdx.x;
    const int wid  = tid >> 5;
    const int lane = tid & 31;
    const int m0 = blockIdx.y * 64;
    const int n0 = blockIdx.x * 64;
    const int wm = wid & 3;
    const int wn = wid >> 2;

    auto load_tile = [&](int kt) {
        const int st = kt & (STG - 1);
        const uint32_t sAh = sbase + st * SBYTES;
        const uint32_t sAl = sAh + ABY;
        const uint32_t sBh = sAl + ABY;
        const uint32_t sBl = sBh + ABY;
        const __nv_bfloat16* Agh = Ah + (size_t)m0 * Ee + kt * 32;
        const __nv_bfloat16* Agl = Al + (size_t)m0 * Ee + kt * 32;
        const __nv_bfloat16* Bgh = Wh + (size_t)n0 * Ee + kt * 32;
        const __nv_bfloat16* Bgl = Wl + (size_t)n0 * Ee + kt * 32;
        int row = tid >> 2, ch = tid & 3;        // 256 thr = 64 rows x 4 chunks
        uint32_t off = row * 64 + ((ch ^ ((row >> 1) & 3)) << 4);
        cp16(sAh + off, Agh + (size_t)row * Ee + ch * 8);
        cp16(sAl + off, Agl + (size_t)row * Ee + ch * 8);
        cp16(sBh + off, Bgh + (size_t)row * Ee + ch * 8);
        cp16(sBl + off, Bgl + (size_t)row * Ee + ch * 8);
        CP_COMMIT();
    };

    float acc[4][4];
    #pragma unroll
    for (int j = 0; j < 4; j++)
        #pragma unroll
        for (int k = 0; k < 4; k++) acc[j][k] = 0.f;

    const int arow = wm * 16 + (lane & 15);
    const int achk = (lane >> 4) & 1;
    int bro[2];
    #pragma unroll
    for (int p = 0; p < 2; p++) bro[p] = wn * 32 + p * 16 + (lane & 7) + ((lane >> 4) & 1) * 8;
    const int bchk = (lane >> 3) & 1;

    #pragma unroll
    for (int kt = 0; kt < STG - 1; kt++) load_tile(kt);

    for (int it = 0; it < NTk; ++it) {
        const int st = it & (STG - 1);
        if (it < NTk - 2)       asm volatile("cp.async.wait_group 2;" ::: "memory");
        else if (it == NTk - 2) asm volatile("cp.async.wait_group 1;" ::: "memory");
        else                    asm volatile("cp.async.wait_group 0;" ::: "memory");
        __syncthreads();

        if (it + STG - 1 < NTk) load_tile(it + STG - 1);

        const uint32_t sAh = sbase + st * SBYTES;
        const uint32_t sAl = sAh + ABY;
        const uint32_t sBh = sAl + ABY;
        const uint32_t sBl = sBh + ABY;

        #pragma unroll
        for (int ks = 0; ks < 2; ks++) {
            uint32_t ah0, ah1, ah2, ah3;
            ldsm4(ah0, ah1, ah2, ah3,
                  sAh + arow * 64 + (((2*ks + achk) ^ ((arow >> 1) & 3)) << 4));
            uint32_t bfh[4][2];
            #pragma unroll
            for (int p = 0; p < 2; p++)
                ldsm4(bfh[2*p][0], bfh[2*p][1], bfh[2*p+1][0], bfh[2*p+1][1],
                      sBh + bro[p] * 64 + (((2*ks + bchk) ^ ((bro[p] >> 1) & 3)) << 4));
            #pragma unroll
            for (int nt = 0; nt < 4; nt++)
                mma_bf16(acc[nt], ah0, ah1, ah2, ah3, bfh[nt][0], bfh[nt][1]);
            uint32_t bfl[4][2];
            #pragma unroll
            for (int p = 0; p < 2; p++)
                ldsm4(bfl[2*p][0], bfl[2*p][1], bfl[2*p+1][0], bfl[2*p+1][1],
                      sBl + bro[p] * 64 + (((2*ks + bchk) ^ ((bro[p] >> 1) & 3)) << 4));
            #pragma unroll
            for (int nt = 0; nt < 4; nt++)
                mma_bf16(acc[nt], ah0, ah1, ah2, ah3, bfl[nt][0], bfl[nt][1]);
            uint32_t al0, al1, al2, al3;
            ldsm4(al0, al1, al2, al3,
                  sAl + arow * 64 + (((2*ks + achk) ^ ((arow >> 1) & 3)) << 4));
            #pragma unroll
            for (int nt = 0; nt < 4; nt++)
                mma_bf16(acc[nt], al0, al1, al2, al3, bfh[nt][0], bfh[nt][1]);
        }
    }

    const int g = lane >> 2, t = lane & 3;
    #pragma unroll
    for (int nt = 0; nt < 4; nt++) {
        const int col = n0 + wn * 32 + nt * 8 + 2 * t;
        float2 bz = *(const float2*)&bias[col];
        const int r0 = m0 + wm * 16 + g;
        float2 v0, v1;
        v0.x = acc[nt][0] + bz.x; v0.y = acc[nt][1] + bz.y;
        v1.x = acc[nt][2] + bz.x; v1.y = acc[nt][3] + bz.y;
        *(float2*)&C[(size_t)r0 * N + col]       = v0;
        *(float2*)&C[(size_t)(r0 + 8) * N + col] = v1;
    }
}

// ---------------- flash attention: tf32 mma.sync, causal, split-KV (round-12) ----------------
// smem: Q 32KB @0 | K[2] 16KB @32K,48K | V[2] 16KB @64K,80K  = 96KB
__global__ void __launch_bounds__(256, 2)
flash_tc()
{
    extern __shared__ float smf[];
    const uint32_t QsB = smem_u32(smf);

    const int tid  = threadIdx.x;
    const int wid  = tid >> 5;
    const int lane = tid & 31;
    const int g = lane >> 2, t = lane & 3;

    const int slot = blockIdx.y;
    const int qt = d_qt[slot];
    const int ch = d_ch[slot];
    const int q0 = qt * 128;
    const bool split = (ch != 2);
    const int t0 = (split && ch == 1) ? (qt + 1) : 0;
    const int t1 = (split && ch == 0) ? (qt + 1) : (2 * qt + 2);

    const int bh = blockIdx.x;
    const int b  = bh / Hh;
    const int h  = bh - b * Hh;

    const float* qg = g_c + (size_t)(b * LLen) * N3E + h * Dd;
    const float* kg = qg + Ee;
    const float* vt = g_vt + (size_t)bh * Dd * LLen;

    const int srow = tid >> 4;
    const int sch  = tid & 15;

    auto load_kv = [&](int kb, int buf) {
        const uint32_t KsB = QsB + 32768u + (uint32_t)buf * 16384u;
        const uint32_t VtB = QsB + 65536u + (uint32_t)buf * 16384u;
        #pragma unroll
        for (int i = 0; i < 4; i++) {
            int r = srow + i * 16;
            cp16(KsB + r * 256 + ((sch ^ ((r & 7) << 1)) << 4),
                 kg + (size_t)(kb + r) * N3E + sch * 4);
        }
        #pragma unroll
        for (int i = 0; i < 4; i++) {
            int d = srow + i * 16;
            cp16(VtB + d * 256 + ((sch ^ ((d & 7) << 1)) << 4),
                 vt + (size_t)d * LLen + kb + sch * 4);
        }
        CP_COMMIT();
    };

    // Q (already tf32-rounded in gmem)
    #pragma unroll
    for (int i = 0; i < 8; i++) {
        int r = srow + i * 16;
        cp16(QsB + r * 256 + ((sch ^ ((r & 7) << 1)) << 4),
             qg + (size_t)(q0 + r) * N3E + sch * 4);
    }
    load_kv(t0 * 64, t0 & 1);

    float m[2] = {-INFINITY, -INFINITY};
    float l[2] = {0.f, 0.f};
    float oacc[8][4];
    #pragma unroll
    for (int j = 0; j < 8; j++)
        #pragma unroll
        for (int k = 0; k < 4; k++) oacc[j][k] = 0.f;

    const int arow = (wid << 4) + (lane & 15);
    const int achk = (lane >> 4) & 1;
    const int asw  = (arow & 7) << 1;
    int brow[4];
    #pragma unroll
    for (int p = 0; p < 4; p++) brow[p] = (p << 4) + (lane & 7) + (((lane >> 4) & 1) << 3);
    const int bchk = (lane >> 3) & 1;

    const int srcA = (lane & ~3) | (t >> 1);
    const int srcB = srcA + 2;
    const bool odd = (t & 1);

    for (int ti = t0; ti < t1; ti++) {
        const int kb = ti * 64;
        const int buf = ti & 1;
        const uint32_t KsB = QsB + 32768u + (uint32_t)buf * 16384u;
        const uint32_t VtB = QsB + 65536u + (uint32_t)buf * 16384u;

        asm volatile("cp.async.wait_group 0;" ::: "memory");
        __syncthreads();
        if (ti + 1 < t1) load_kv(kb + 64, buf ^ 1);

        if (q0 + (wid << 4) + 15 < kb) continue;

        // ---- S = Q K^T ----
        float sacc[8][4];
        #pragma unroll
        for (int j = 0; j < 8; j++)
            #pragma unroll
            for (int k = 0; k < 4; k++) sacc[j][k] = 0.f;

        #pragma unroll
        for (int ks = 0; ks < 8; ks++) {
            uint32_t a0, a1, a2, a3;
            ldsm4(a0, a1, a2, a3,
                  QsB + arow * 256 + ((((ks << 1) + achk) ^ asw) << 4));
            uint32_t bf[8][2];
            #pragma unroll
            for (int p = 0; p < 4; p++)
                ldsm4(bf[2*p][0], bf[2*p][1], bf[2*p+1][0], bf[2*p+1][1],
                      KsB + brow[p] * 256 + ((((ks << 1) + bchk) ^ ((brow[p] & 7) << 1)) << 4));
            #pragma unroll
            for (int j = 0; j < 8; j++)
                mma_tf32(sacc[j], a0, a1, a2, a3, bf[j][0], bf[j][1]);
        }

        if (kb >= q0) {
            const int r0g = q0 + (wid << 4) + g;
            #pragma unroll
            for (int j = 0; j < 8; j++) {
                int cg = kb + (j << 3) + (t << 1);
                if (cg > r0g)         sacc[j][0] = -1e9f;
                if (cg + 1 > r0g)     sacc[j][1] = -1e9f;
                if (cg > r0g + 8)     sacc[j][2] = -1e9f;
                if (cg + 1 > r0g + 8) sacc[j][3] = -1e9f;
            }
        }

        // ---- online softmax (rows g and g+8); l summed over ROUNDED p ----
        float mt0 = -INFINITY, mt1 = -INFINITY;
        #pragma unroll
        for (int j = 0; j < 8; j++) {
            mt0 = fmaxf(mt0, fmaxf(sacc[j][0], sacc[j][1]));
            mt1 = fmaxf(mt1, fmaxf(sacc[j][2], sacc[j][3]));
        }
        mt0 = fmaxf(mt0, __shfl_xor_sync(0xffffffffu, mt0, 1));
        mt0 = fmaxf(mt0, __shfl_xor_sync(0xffffffffu, mt0, 2));
        mt1 = fmaxf(mt1, __shfl_xor_sync(0xffffffffu, mt1, 1));
        mt1 = fmaxf(mt1, __shfl_xor_sync(0xffffffffu, mt1, 2));
        float mn0 = fmaxf(m[0], mt0), mn1 = fmaxf(m[1], mt1);
        float sc0 = __expf(m[0] - mn0), sc1 = __expf(m[1] - mn1);
        m[0] = mn0; m[1] = mn1;
        float ls0 = 0.f, ls1 = 0.f;
        #pragma unroll
        for (int j = 0; j < 8; j++) {
            sacc[j][0] = rna(__expf(sacc[j][0] - mn0)); ls0 += sacc[j][0];
            sacc[j][1] = rna(__expf(sacc[j][1] - mn0)); ls0 += sacc[j][1];
            sacc[j][2] = rna(__expf(sacc[j][2] - mn1)); ls1 += sacc[j][2];
            sacc[j][3] = rna(__expf(sacc[j][3] - mn1)); ls1 += sacc[j][3];
        }
        ls0 += __shfl_xor_sync(0xffffffffu, ls0, 1);
        ls0 += __shfl_xor_sync(0xffffffffu, ls0, 2);
        ls1 += __shfl_xor_sync(0xffffffffu, ls1, 1);
        ls1 += __shfl_xor_sync(0xffffffffu, ls1, 2);
        l[0] = l[0] * sc0 + ls0;
        l[1] = l[1] * sc1 + ls1;
        #pragma unroll
        for (int j = 0; j < 8; j++) {
            oacc[j][0] *= sc0; oacc[j][1] *= sc0;
            oacc[j][2] *= sc1; oacc[j][3] *= sc1;
        }

        // ---- O += P V : P C-frag -> A-frag via shuffles, then MMA ----
        #pragma unroll
        for (int ks = 0; ks < 8; ks++) {
            float v0 = __shfl_sync(0xffffffffu, sacc[ks][0], srcA);
            float v1 = __shfl_sync(0xffffffffu, sacc[ks][1], srcA);
            float v2 = __shfl_sync(0xffffffffu, sacc[ks][2], srcA);
            float v3 = __shfl_sync(0xffffffffu, sacc[ks][3], srcA);
            float w0 = __shfl_sync(0xffffffffu, sacc[ks][0], srcB);
            float w1 = __shfl_sync(0xffffffffu, sacc[ks][1], srcB);
            float w2 = __shfl_sync(0xffffffffu, sacc[ks][2], srcB);
            float w3 = __shfl_sync(0xffffffffu, sacc[ks][3], srcB);
            uint32_t pa0 = __float_as_uint(odd ? v1 : v0);
            uint32_t pa1 = __float_as_uint(odd ? v3 : v2);
            uint32_t pa2 = __float_as_uint(odd ? w1 : w0);
            uint32_t pa3 = __float_as_uint(odd ? w3 : w2);

            uint32_t vf[8][2];
            #pragma unroll
            for (int p = 0; p < 4; p++)
                ldsm4(vf[2*p][0], vf[2*p][1], vf[2*p+1][0], vf[2*p+1][1],
                      VtB + brow[p] * 256 + ((((ks << 1) + bchk) ^ ((brow[p] & 7) << 1)) << 4));
            #pragma unroll
            for (int j = 0; j < 8; j++)
                mma_tf32(oacc[j], pa0, pa1, pa2, pa3, vf[j][0], vf[j][1]);
        }
    }

    const int lr0 = (wid << 4) + g;
    const int lr1 = lr0 + 8;
    if (split) {
        const int pidx = (bh * 8 + (qt - 8)) * 2 + ch;
        float* po = g_po + (size_t)pidx * 128 * 64;
        #pragma unroll
        for (int j = 0; j < 8; j++) {
            int d = (j << 3) + (t << 1);
            *(float2*)&po[lr0 * 64 + d] = make_float2(oacc[j][0], oacc[j][1]);
            *(float2*)&po[lr1 * 64 + d] = make_float2(oacc[j][2], oacc[j][3]);
        }
        if (t == 0) {
            g_pm[pidx * 128 + lr0] = m[0]; g_pl[pidx * 128 + lr0] = l[0];
            g_pm[pidx * 128 + lr1] = m[1]; g_pl[pidx * 128 + lr1] = l[1];
        }
    } else {
        const float inv0 = 1.f / l[0], inv1 = 1.f / l[1];
        const int grow = b * LLen + q0 + lr0;
        __nv_bfloat16* ah0 = g_ah + (size_t)grow * Ee + h * Dd;
        __nv_bfloat16* al0 = g_al + (size_t)grow * Ee + h * Dd;
        __nv_bfloat16* ah1 = ah0 + 8 * Ee;
        __nv_bfloat16* al1 = al0 + 8 * Ee;
        #pragma unroll
        for (int j = 0; j < 8; j++) {
            int d = (j << 3) + (t << 1);
            float o0 = oacc[j][0] * inv0, o1 = oacc[j][1] * inv0;
            float o2 = oacc[j][2] * inv1, o3 = oacc[j][3] * inv1;
            __nv_bfloat16 h0,l0b,h1,l1b,h2,l2b,h3,l3b;
            bf16_split(o0, h0, l0b); bf16_split(o1, h1, l1b);
            bf16_split(o2, h2, l2b); bf16_split(o3, h3, l3b);
            *(__nv_bfloat162*)&ah0[d] = __nv_bfloat162(h0, h1);
            *(__nv_bfloat162*)&al0[d] = __nv_bfloat162(l0b, l1b);
            *(__nv_bfloat162*)&ah1[d] = __nv_bfloat162(h2, h3);
            *(__nv_bfloat162*)&al1[d] = __nv_bfloat162(l2b, l3b);
        }
    }
}

// ---------------- merge split-KV partials ----------------
__global__ void merge_kv()
{
    const int s  = blockIdx.x;
    const int bh = blockIdx.y;
    const int qt = 8 + s;
    const int b = bh / Hh, h = bh - b * Hh;
    const int p0 = (bh * 8 + s) * 2;
    const int p1 = p0 + 1;
    const int r  = threadIdx.x >> 1;
    const int c0 = (threadIdx.x & 1) * 32;

    float m1 = g_pm[p0 * 128 + r], l1 = g_pl[p0 * 128 + r];
    float m2 = g_pm[p1 * 128 + r], l2 = g_pl[p1 * 128 + r];
    float mm = fmaxf(m1, m2);
    float e1 = __expf(m1 - mm), e2 = __expf(m2 - mm);
    float inv = 1.f / (l1 * e1 + l2 * e2);

    const float* o1 = g_po + ((size_t)p0 * 128 + r) * 64 + c0;
    const float* o2 = g_po + ((size_t)p1 * 128 + r) * 64 + c0;
    const int grow = b * LLen + qt * 128 + r;
    __nv_bfloat16* ah = g_ah + (size_t)grow * Ee + h * Dd + c0;
    __nv_bfloat16* al = g_al + (size_t)grow * Ee + h * Dd + c0;

    #pragma unroll
    for (int c = 0; c < 32; c += 2) {
        float2 a = *(const float2*)&o1[c];
        float2 bx = *(const float2*)&o2[c];
        float v0 = (a.x * e1 + bx.x * e2) * inv;
        float v1 = (a.y * e1 + bx.y * e2) * inv;
        __nv_bfloat16 h0, l0, h1, l1b;
        bf16_split(v0, h0, l0); bf16_split(v1, h1, l1b);
        *(__nv_bfloat162*)&ah[c] = __nv_bfloat162(h0, h1);
        *(__nv_bfloat162*)&al[c] = __nv_bfloat162(l0, l1b);
    }
}

// ---------------- launch ----------------
extern "C" void kernel_launch(void* const* d_in, const int* in_sizes, int n_in,
                              void* d_out, int out_size)
{
    const float* x     = (const float*)d_in[0];
    const float* w_in  = (const float*)d_in[1];
    const float* b_in  = (const float*)d_in[2];
    const float* A_in  = (const float*)d_in[3];
    const float* B_in  = (const float*)d_in[4];
    const float* w_out = (const float*)d_in[5];
    const float* b_out = (const float*)d_in[6];
    const float* A_out = (const float*)d_in[7];
    const float* B_out = (const float*)d_in[8];
    float* out = (float*)d_out;

    __nv_bfloat16 *p_w1h, *p_w1l, *p_w2h, *p_w2l, *p_xh, *p_xl, *p_ah, *p_al;
    float *p_c;
    cudaGetSymbolAddress((void**)&p_w1h, g_w1h);
    cudaGetSymbolAddress((void**)&p_w1l, g_w1l);
    cudaGetSymbolAddress((void**)&p_w2h, g_w2h);
    cudaGetSymbolAddress((void**)&p_w2l, g_w2l);
    cudaGetSymbolAddress((void**)&p_xh,  g_xh);
    cudaGetSymbolAddress((void**)&p_xl,  g_xl);
    cudaGetSymbolAddress((void**)&p_c,   g_c);
    cudaGetSymbolAddress((void**)&p_ah,  g_ah);
    cudaGetSymbolAddress((void**)&p_al,  g_al);

    const int smem1 = 3 * (2 * 128 * 64 + 2 * 128 * 64);   // 98304
    const int smem2 = 4 * 4 * 64 * 64;                      // 65536
    const int smemF = 98304;                                // Q + 2K + 2V
    cudaFuncSetAttribute((const void*)gemm_tc1,
                         cudaFuncAttributeMaxDynamicSharedMemorySize, smem1);
    cudaFuncSetAttribute((const void*)gemm_tc2,
                         cudaFuncAttributeMaxDynamicSharedMemorySize, smem2);
    cudaFuncSetAttribute((const void*)flash_tc,
                         cudaFuncAttributeMaxDynamicSharedMemorySize, smemF);

    {
        dim3 blk(32, 8);
        dim3 gp(N3E / 32, Ee / 32, 2);
        prep_wt2<<<gp, blk>>>(w_in, A_in, B_in, p_w1h, p_w1l,
                              w_out, A_out, B_out, p_w2h, p_w2l);
        cvt_x<<<Mrows * Ee / 4 / 256, 256>>>((const float4*)x, p_xh, p_xl);
    }
    {
        dim3 grid(N3E / 128, Mrows / 128);
        gemm_tc1<<<grid, 256, smem1>>>(p_xh, p_xl, p_w1h, p_w1l, b_in, p_c, N3E);
    }
    {
        dim3 blk(32, 8);
        dim3 gv(LLen / 32, 2 * Bb * Hh);
        vtrans<<<gv, blk>>>();
    }
    {
        dim3 grid(Bb * Hh, 24);
        flash_tc<<<grid, 256, smemF>>>();
        merge_kv<<<dim3(8, Bb * Hh), 256>>>();
    }
    {
        dim3 grid(Ee / 64, Mrows / 64);   // 12 x 64 = 768 CTAs, better wave balance
        gemm_tc2<<<grid, 256, smem2>>>(p_ah, p_al, p_w2h, p_w2l, b_out, out, Ee);
    }
}

// round 16
// speedup vs baseline: 1.0634x; 1.0139x over previous
#include <cuda_runtime.h>
#include <cuda_bf16.h>
#include <cstdint>
#include <math.h>

#define Hh 12
#define Ee 768
#define Dd 64
#define LLen 2048
#define Bb 2
#define Mrows (Bb*LLen)      // 4096
#define N3E (3*Ee)           // 2304
#define LORA 8.0f

// ---------------- scratch ----------------
__device__ __nv_bfloat16 g_w1h[N3E * Ee], g_w1l[N3E * Ee];
__device__ __nv_bfloat16 g_w2h[Ee * Ee],  g_w2l[Ee * Ee];
__device__ __nv_bfloat16 g_xh [Mrows * Ee], g_xl [Mrows * Ee];
__device__ float g_c [Mrows * N3E];                  // qkv (v-region unused), tf32-rounded
__device__ float g_vt[Bb * Hh * Dd * LLen];          // V transposed: [bh*64+d][token]
__device__ __nv_bfloat16 g_ah [Mrows * Ee], g_al [Mrows * Ee];
// split-KV partials: 24 bh x 8 split-qt x 2 chunks
__device__ float g_po[384 * 128 * 64];
__device__ float g_pm[384 * 128];
__device__ float g_pl[384 * 128];

// slot schedule (size-descending): qt per slot; ch: 0/1 = split chunk, 2 = unsplit
__device__ const int d_qt[24] = {15,15,7,14,14,6,13,13,5,12,12,11,11,4,10,10,9,9,8,8,3,2,1,0};
__device__ const int d_ch[24] = { 0, 1,2, 0, 1,2, 0, 1,2, 0, 1, 0, 1,2, 0, 1,0,1,0,1,2,2,2,2};

// =================== helpers ===================
__device__ __forceinline__ uint32_t smem_u32(const void* p) {
    uint32_t a;
    asm("{ .reg .u64 t; cvta.to.shared.u64 t, %1; cvt.u32.u64 %0, t; }" : "=r"(a) : "l"(p));
    return a;
}
__device__ __forceinline__ float rna(float x) {
    uint32_t r;
    asm("cvt.rna.tf32.f32 %0, %1;" : "=r"(r) : "f"(x));
    return __uint_as_float(r);
}
__device__ __forceinline__ void cp16(uint32_t dst, const void* src) {
    asm volatile("cp.async.cg.shared.global [%0], [%1], 16;" :: "r"(dst), "l"(src));
}
#define CP_COMMIT() asm volatile("cp.async.commit_group;" ::: "memory")

__device__ __forceinline__ void ldsm4(uint32_t& r0, uint32_t& r1, uint32_t& r2, uint32_t& r3,
                                      uint32_t addr) {
    asm volatile("ldmatrix.sync.aligned.m8n8.x4.shared.b16 {%0,%1,%2,%3}, [%4];"
                 : "=r"(r0), "=r"(r1), "=r"(r2), "=r"(r3) : "r"(addr));
}
__device__ __forceinline__ void mma_tf32(float* c, uint32_t a0, uint32_t a1, uint32_t a2,
                                         uint32_t a3, uint32_t b0, uint32_t b1) {
    asm volatile("mma.sync.aligned.m16n8k8.row.col.f32.tf32.tf32.f32 "
                 "{%0,%1,%2,%3}, {%4,%5,%6,%7}, {%8,%9}, {%0,%1,%2,%3};"
                 : "+f"(c[0]), "+f"(c[1]), "+f"(c[2]), "+f"(c[3])
                 : "r"(a0), "r"(a1), "r"(a2), "r"(a3), "r"(b0), "r"(b1));
}
__device__ __forceinline__ void mma_bf16(float* c, uint32_t a0, uint32_t a1, uint32_t a2,
                                         uint32_t a3, uint32_t b0, uint32_t b1) {
    asm volatile("mma.sync.aligned.m16n8k16.row.col.f32.bf16.bf16.f32 "
                 "{%0,%1,%2,%3}, {%4,%5,%6,%7}, {%8,%9}, {%0,%1,%2,%3};"
                 : "+f"(c[0]), "+f"(c[1]), "+f"(c[2]), "+f"(c[3])
                 : "r"(a0), "r"(a1), "r"(a2), "r"(a3), "r"(b0), "r"(b1));
}
__device__ __forceinline__ void bf16_split(float f, __nv_bfloat16& h, __nv_bfloat16& l) {
    h = __float2bfloat16(f);
    l = __float2bfloat16(f - __bfloat162float(h));
}

// ---------------- prep (merged): wt = (w + 8*B@A)^T split into bf16 hi/lo ----------------
__global__ void prep_wt2(const float* __restrict__ w1, const float* __restrict__ A1,
                         const float* __restrict__ B1, __nv_bfloat16* __restrict__ w1h,
                         __nv_bfloat16* __restrict__ w1l,
                         const float* __restrict__ w2, const float* __restrict__ A2,
                         const float* __restrict__ B2, __nv_bfloat16* __restrict__ w2h,
                         __nv_bfloat16* __restrict__ w2l)
{
    const int z = blockIdx.z;
    const float* w  = z ? w2 : w1;
    const float* Aa = z ? A2 : A1;
    const float* Bm = z ? B2 : B1;
    __nv_bfloat16* wh = z ? w2h : w1h;
    __nv_bfloat16* wl = z ? w2l : w1l;
    const int ncols = z ? Ee : N3E;

    __shared__ float t[32][33];
    int o0 = blockIdx.x * 32, e0 = blockIdx.y * 32;
    if (o0 >= ncols) return;
    int tx = threadIdx.x, ty = threadIdx.y;
    #pragma unroll
    for (int r = 0; r < 4; r++) {
        int e = e0 + ty + r * 8, o = o0 + tx;
        float s = 0.f;
        #pragma unroll
        for (int q = 0; q < 4; q++) s += Bm[e*4 + q] * Aa[q*ncols + o];
        t[ty + r*8][tx] = w[(size_t)e * ncols + o] + LORA * s;
    }
    __syncthreads();
    #pragma unroll
    for (int r = 0; r < 4; r++) {
        int o = o0 + ty + r * 8, e = e0 + tx;
        __nv_bfloat16 hh, ll;
        bf16_split(t[tx][ty + r*8], hh, ll);
        wh[(size_t)o * Ee + e] = hh;
        wl[(size_t)o * Ee + e] = ll;
    }
}

// ---------------- x -> bf16 hi/lo split ----------------
__global__ void cvt_x(const float4* __restrict__ in, __nv_bfloat16* __restrict__ oh,
                      __nv_bfloat16* __restrict__ ol)
{
    int i = blockIdx.x * blockDim.x + threadIdx.x;
    float4 v = in[i];
    __nv_bfloat16 h0,l0,h1,l1,h2,l2,h3,l3;
    bf16_split(v.x, h0, l0); bf16_split(v.y, h1, l1);
    bf16_split(v.z, h2, l2); bf16_split(v.w, h3, l3);
    int o = i * 4;
    *(__nv_bfloat162*)&oh[o]     = __nv_bfloat162(h0, h1);
    *(__nv_bfloat162*)&oh[o + 2] = __nv_bfloat162(h2, h3);
    *(__nv_bfloat162*)&ol[o]     = __nv_bfloat162(l0, l1);
    *(__nv_bfloat162*)&ol[o + 2] = __nv_bfloat162(l2, l3);
}

// ---------------- bf16x2 mma.sync GEMM1: 128x128 tile + fused V transpose ----------------
#define NTk 24   // 768/32

__global__ void __launch_bounds__(256, 2)
gemm_tc1(const __nv_bfloat16* __restrict__ Ah, const __nv_bfloat16* __restrict__ Al,
         const __nv_bfloat16* __restrict__ Wh, const __nv_bfloat16* __restrict__ Wl,
         const float* __restrict__ bias, float* __restrict__ C, int N)
{
    constexpr int MT = 4;
    constexpr int ABY = 128 * 64;
    constexpr int BBY = 128 * 64;
    constexpr int SBYTES = 2 * ABY + 2 * BBY;
    constexpr int STG = 3;

    extern __shared__ float sm[];
    const uint32_t sbase = smem_u32(sm);

    const int tid  = threadIdx.x;
    const int wid  = tid >> 5;
    const int lane = tid & 31;
    const int m0 = blockIdx.y * 128;
    const int n0 = blockIdx.x * 128;
    const int wm = wid & 1;
    const int wn = wid >> 1;

    auto load_tile = [&](int kt) {
        const int st = kt % STG;
        const uint32_t sAh = sbase + st * SBYTES;
        const uint32_t sAl = sAh + ABY;
        const uint32_t sBh = sAl + ABY;
        const uint32_t sBl = sBh + BBY;
        const __nv_bfloat16* Agh = Ah + (size_t)m0 * Ee + kt * 32;
        const __nv_bfloat16* Agl = Al + (size_t)m0 * Ee + kt * 32;
        const __nv_bfloat16* Bgh = Wh + (size_t)n0 * Ee + kt * 32;
        const __nv_bfloat16* Bgl = Wl + (size_t)n0 * Ee + kt * 32;
        #pragma unroll
        for (int i = 0; i < 2; i++) {
            int f = tid + i * 256;
            int row = f >> 2, ch = f & 3;
            uint32_t off = row * 64 + ((ch ^ ((row >> 1) & 3)) << 4);
            cp16(sAh + off, Agh + (size_t)row * Ee + ch * 8);
            cp16(sAl + off, Agl + (size_t)row * Ee + ch * 8);
            cp16(sBh + off, Bgh + (size_t)row * Ee + ch * 8);
            cp16(sBl + off, Bgl + (size_t)row * Ee + ch * 8);
        }
        CP_COMMIT();
    };

    float acc[MT][4][4];
    #pragma unroll
    for (int i = 0; i < MT; i++)
        #pragma unroll
        for (int j = 0; j < 4; j++)
            #pragma unroll
            for (int k = 0; k < 4; k++) acc[i][j][k] = 0.f;

    int arow[MT], bro[2];
    #pragma unroll
    for (int mt = 0; mt < MT; mt++) arow[mt] = wm * MT * 16 + mt * 16 + (lane & 15);
    const int achk = (lane >> 4) & 1;
    #pragma unroll
    for (int p = 0; p < 2; p++) bro[p] = wn * 32 + p * 16 + (lane & 7) + ((lane >> 4) & 1) * 8;
    const int bchk = (lane >> 3) & 1;

    #pragma unroll
    for (int kt = 0; kt < STG - 1; kt++) load_tile(kt);

    for (int it = 0; it < NTk; ++it) {
        const int st = it % STG;
        if (it < NTk - 1) asm volatile("cp.async.wait_group 1;" ::: "memory");
        else              asm volatile("cp.async.wait_group 0;" ::: "memory");
        __syncthreads();

        if (it + STG - 1 < NTk) load_tile(it + STG - 1);

        const uint32_t sAh = sbase + st * SBYTES;
        const uint32_t sAl = sAh + ABY;
        const uint32_t sBh = sAl + ABY;
        const uint32_t sBl = sBh + BBY;

        #pragma unroll
        for (int ks = 0; ks < 2; ks++) {
            uint32_t afh[MT][4];
            #pragma unroll
            for (int mt = 0; mt < MT; mt++)
                ldsm4(afh[mt][0], afh[mt][1], afh[mt][2], afh[mt][3],
                      sAh + arow[mt] * 64 + (((2*ks + achk) ^ ((arow[mt] >> 1) & 3)) << 4));
            uint32_t bfh[4][2];
            #pragma unroll
            for (int p = 0; p < 2; p++)
                ldsm4(bfh[2*p][0], bfh[2*p][1], bfh[2*p+1][0], bfh[2*p+1][1],
                      sBh + bro[p] * 64 + (((2*ks + bchk) ^ ((bro[p] >> 1) & 3)) << 4));
            #pragma unroll
            for (int mt = 0; mt < MT; mt++)
                #pragma unroll
                for (int nt = 0; nt < 4; nt++)
                    mma_bf16(acc[mt][nt], afh[mt][0], afh[mt][1], afh[mt][2], afh[mt][3],
                             bfh[nt][0], bfh[nt][1]);
            uint32_t bfl[4][2];
            #pragma unroll
            for (int p = 0; p < 2; p++)
                ldsm4(bfl[2*p][0], bfl[2*p][1], bfl[2*p+1][0], bfl[2*p+1][1],
                      sBl + bro[p] * 64 + (((2*ks + bchk) ^ ((bro[p] >> 1) & 3)) << 4));
            #pragma unroll
            for (int mt = 0; mt < MT; mt++)
                #pragma unroll
                for (int nt = 0; nt < 4; nt++)
                    mma_bf16(acc[mt][nt], afh[mt][0], afh[mt][1], afh[mt][2], afh[mt][3],
                             bfl[nt][0], bfl[nt][1]);
            uint32_t afl[MT][4];
            #pragma unroll
            for (int mt = 0; mt < MT; mt++)
                ldsm4(afl[mt][0], afl[mt][1], afl[mt][2], afl[mt][3],
                      sAl + arow[mt] * 64 + (((2*ks + achk) ^ ((arow[mt] >> 1) & 3)) << 4));
            #pragma unroll
            for (int mt = 0; mt < MT; mt++)
                #pragma unroll
                for (int nt = 0; nt < 4; nt++)
                    mma_bf16(acc[mt][nt], afl[mt][0], afl[mt][1], afl[mt][2], afl[mt][3],
                             bfh[nt][0], bfh[nt][1]);
        }
    }

    const int g = lane >> 2, t = lane & 3;
    if (n0 < 2 * Ee) {
        // q/k region: direct store to g_c (rna'd)
        #pragma unroll
        for (int nt = 0; nt < 4; nt++) {
            const int col = n0 + wn * 32 + nt * 8 + 2 * t;
            float2 bz = *(const float2*)&bias[col];
            #pragma unroll
            for (int mt = 0; mt < MT; mt++) {
                const int r0 = m0 + wm * MT * 16 + mt * 16 + g;
                float2 v0, v1;
                v0.x = rna(acc[mt][nt][0] + bz.x); v0.y = rna(acc[mt][nt][1] + bz.y);
                v1.x = rna(acc[mt][nt][2] + bz.x); v1.y = rna(acc[mt][nt][3] + bz.y);
                *(float2*)&C[(size_t)r0 * N + col]       = v0;
                *(float2*)&C[(size_t)(r0 + 8) * N + col] = v1;
            }
        }
    } else {
        // v region: stage tile in smem, write transposed to g_vt (coalesced)
        __syncthreads();   // all warps done with pipeline smem
        #pragma unroll
        for (int nt = 0; nt < 4; nt++) {
            const int col = wn * 32 + nt * 8 + 2 * t;          // local 0..127
            float2 bz = *(const float2*)&bias[n0 + col];
            #pragma unroll
            for (int mt = 0; mt < MT; mt++) {
                const int r0 = wm * MT * 16 + mt * 16 + g;     // local 0..127
                sm[r0 * 129 + col]           = rna(acc[mt][nt][0] + bz.x);
                sm[r0 * 129 + col + 1]       = rna(acc[mt][nt][1] + bz.y);
                sm[(r0 + 8) * 129 + col]     = rna(acc[mt][nt][2] + bz.x);
                sm[(r0 + 8) * 129 + col + 1] = rna(acc[mt][nt][3] + bz.y);
            }
        }
        __syncthreads();
        const int b2   = m0 >> 11;          // batch
        const int tokb = m0 & 2047;         // token base within batch
        const int cvb  = n0 - 2 * Ee;       // v-col base (multiple of 128)
        #pragma unroll
        for (int rr = 0; rr < 16; rr++) {
            const int dd = (wid << 4) + rr;             // local v-col 0..127
            const int cv = cvb + dd;
            const int h2 = cv >> 6, d2 = cv & 63;
            float4 v;
            v.x = sm[(lane * 4 + 0) * 129 + dd];
            v.y = sm[(lane * 4 + 1) * 129 + dd];
            v.z = sm[(lane * 4 + 2) * 129 + dd];
            v.w = sm[(lane * 4 + 3) * 129 + dd];
            *(float4*)&g_vt[(size_t)((b2 * Hh + h2) * Dd + d2) * LLen + tokb + lane * 4] = v;
        }
    }
}

// ---------------- bf16x2 mma.sync GEMM2: 128x64 tile (round-12 form) ----------------
__global__ void __launch_bounds__(256, 2)
gemm_tc2(const __nv_bfloat16* __restrict__ Ah, const __nv_bfloat16* __restrict__ Al,
         const __nv_bfloat16* __restrict__ Wh, const __nv_bfloat16* __restrict__ Wl,
         const float* __restrict__ bias, float* __restrict__ C, int N)
{
    constexpr int MT = 2;
    constexpr int ABY = 128 * 64;
    constexpr int BBY = 64 * 64;
    constexpr int SBYTES = 2 * ABY + 2 * BBY;
    constexpr int STG = 4;

    extern __shared__ float sm[];
    const uint32_t sbase = smem_u32(sm);

    const int tid  = threadIdx.x;
    const int wid  = tid >> 5;
    const int lane = tid & 31;
    const int m0 = blockIdx.y * 128;
    const int n0 = blockIdx.x * 64;
    const int wm = wid & 3;
    const int wn = wid >> 2;

    auto load_tile = [&](int kt) {
        const int st = kt & (STG - 1);
        const uint32_t sAh = sbase + st * SBYTES;
        const uint32_t sAl = sAh + ABY;
        const uint32_t sBh = sAl + ABY;
        const uint32_t sBl = sBh + BBY;
        const __nv_bfloat16* Agh = Ah + (size_t)m0 * Ee + kt * 32;
        const __nv_bfloat16* Agl = Al + (size_t)m0 * Ee + kt * 32;
        const __nv_bfloat16* Bgh = Wh + (size_t)n0 * Ee + kt * 32;
        const __nv_bfloat16* Bgl = Wl + (size_t)n0 * Ee + kt * 32;
        #pragma unroll
        for (int i = 0; i < 2; i++) {
            int f = tid + i * 256;
            int row = f >> 2, ch = f & 3;
            uint32_t off = row * 64 + ((ch ^ ((row >> 1) & 3)) << 4);
            cp16(sAh + off, Agh + (size_t)row * Ee + ch * 8);
            cp16(sAl + off, Agl + (size_t)row * Ee + ch * 8);
        }
        {
            int row = tid >> 2, ch = tid & 3;   // 64 rows x 4 chunks
            uint32_t off = row * 64 + ((ch ^ ((row >> 1) & 3)) << 4);
            cp16(sBh + off, Bgh + (size_t)row * Ee + ch * 8);
            cp16(sBl + off, Bgl + (size_t)row * Ee + ch * 8);
        }
        CP_COMMIT();
    };

    float acc[MT][4][4];
    #pragma unroll
    for (int i = 0; i < MT; i++)
        #pragma unroll
        for (int j = 0; j < 4; j++)
            #pragma unroll
            for (int k = 0; k < 4; k++) acc[i][j][k] = 0.f;

    int arow[MT], bro[2];
    #pragma unroll
    for (int mt = 0; mt < MT; mt++) arow[mt] = wm * MT * 16 + mt * 16 + (lane & 15);
    const int achk = (lane >> 4) & 1;
    #pragma unroll
    for (int p = 0; p < 2; p++) bro[p] = wn * 32 + p * 16 + (lane & 7) + ((lane >> 4) & 1) * 8;
    const int bchk = (lane >> 3) & 1;

    #pragma unroll
    for (int kt = 0; kt < STG - 1; kt++) load_tile(kt);

    for (int it = 0; it < NTk; ++it) {
        const int st = it & (STG - 1);
        if (it < NTk - 2)       asm volatile("cp.async.wait_group 2;" ::: "memory");
        else if (it == NTk - 2) asm volatile("cp.async.wait_group 1;" ::: "memory");
        else                    asm volatile("cp.async.wait_group 0;" ::: "memory");
        __syncthreads();

        if (it + STG - 1 < NTk) load_tile(it + STG - 1);

        const uint32_t sAh = sbase + st * SBYTES;
        const uint32_t sAl = sAh + ABY;
        const uint32_t sBh = sAl + ABY;
        const uint32_t sBl = sBh + BBY;

        #pragma unroll
        for (int ks = 0; ks < 2; ks++) {
            uint32_t afh[MT][4];
            #pragma unroll
            for (int mt = 0; mt < MT; mt++)
                ldsm4(afh[mt][0], afh[mt][1], afh[mt][2], afh[mt][3],
                      sAh + arow[mt] * 64 + (((2*ks + achk) ^ ((arow[mt] >> 1) & 3)) << 4));
            uint32_t bfh[4][2];
            #pragma unroll
            for (int p = 0; p < 2; p++)
                ldsm4(bfh[2*p][0], bfh[2*p][1], bfh[2*p+1][0], bfh[2*p+1][1],
                      sBh + bro[p] * 64 + (((2*ks + bchk) ^ ((bro[p] >> 1) & 3)) << 4));
            #pragma unroll
            for (int mt = 0; mt < MT; mt++)
                #pragma unroll
                for (int nt = 0; nt < 4; nt++)
                    mma_bf16(acc[mt][nt], afh[mt][0], afh[mt][1], afh[mt][2], afh[mt][3],
                             bfh[nt][0], bfh[nt][1]);
            uint32_t bfl[4][2];
            #pragma unroll
            for (int p = 0; p < 2; p++)
                ldsm4(bfl[2*p][0], bfl[2*p][1], bfl[2*p+1][0], bfl[2*p+1][1],
                      sBl + bro[p] * 64 + (((2*ks + bchk) ^ ((bro[p] >> 1) & 3)) << 4));
            #pragma unroll
            for (int mt = 0; mt < MT; mt++)
                #pragma unroll
                for (int nt = 0; nt < 4; nt++)
                    mma_bf16(acc[mt][nt], afh[mt][0], afh[mt][1], afh[mt][2], afh[mt][3],
                             bfl[nt][0], bfl[nt][1]);
            uint32_t afl[MT][4];
            #pragma unroll
            for (int mt = 0; mt < MT; mt++)
                ldsm4(afl[mt][0], afl[mt][1], afl[mt][2], afl[mt][3],
                      sAl + arow[mt] * 64 + (((2*ks + achk) ^ ((arow[mt] >> 1) & 3)) << 4));
            #pragma unroll
            for (int mt = 0; mt < MT; mt++)
                #pragma unroll
                for (int nt = 0; nt < 4; nt++)
                    mma_bf16(acc[mt][nt], afl[mt][0], afl[mt][1], afl[mt][2], afl[mt][3],
                             bfh[nt][0], bfh[nt][1]);
        }
    }

    const int g = lane >> 2, t = lane & 3;
    #pragma unroll
    for (int nt = 0; nt < 4; nt++) {
        const int col = n0 + wn * 32 + nt * 8 + 2 * t;
        float2 bz = *(const float2*)&bias[col];
        #pragma unroll
        for (int mt = 0; mt < MT; mt++) {
            const int r0 = m0 + wm * MT * 16 + mt * 16 + g;
            float2 v0, v1;
            v0.x = acc[mt][nt][0] + bz.x; v0.y = acc[mt][nt][1] + bz.y;
            v1.x = acc[mt][nt][2] + bz.x; v1.y = acc[mt][nt][3] + bz.y;
            *(float2*)&C[(size_t)r0 * N + col]       = v0;
            *(float2*)&C[(size_t)(r0 + 8) * N + col] = v1;
        }
    }
}

// ---------------- flash attention: tf32 mma.sync, causal, split-KV (round-12) ----------------
// smem: Q 32KB @0 | K[2] 16KB @32K,48K | V[2] 16KB @64K,80K  = 96KB
__global__ void __launch_bounds__(256, 2)
flash_tc()
{
    extern __shared__ float smf[];
    const uint32_t QsB = smem_u32(smf);

    const int tid  = threadIdx.x;
    const int wid  = tid >> 5;
    const int lane = tid & 31;
    const int g = lane >> 2, t = lane & 3;

    const int slot = blockIdx.y;
    const int qt = d_qt[slot];
    const int ch = d_ch[slot];
    const int q0 = qt * 128;
    const bool split = (ch != 2);
    const int t0 = (split && ch == 1) ? (qt + 1) : 0;
    const int t1 = (split && ch == 0) ? (qt + 1) : (2 * qt + 2);

    const int bh = blockIdx.x;
    const int b  = bh / Hh;
    const int h  = bh - b * Hh;

    const float* qg = g_c + (size_t)(b * LLen) * N3E + h * Dd;
    const float* kg = qg + Ee;
    const float* vt = g_vt + (size_t)bh * Dd * LLen;

    const int srow = tid >> 4;
    const int sch  = tid & 15;

    auto load_kv = [&](int kb, int buf) {
        const uint32_t KsB = QsB + 32768u + (uint32_t)buf * 16384u;
        const uint32_t VtB = QsB + 65536u + (uint32_t)buf * 16384u;
        #pragma unroll
        for (int i = 0; i < 4; i++) {
            int r = srow + i * 16;
            cp16(KsB + r * 256 + ((sch ^ ((r & 7) << 1)) << 4),
                 kg + (size_t)(kb + r) * N3E + sch * 4);
        }
        #pragma unroll
        for (int i = 0; i < 4; i++) {
            int d = srow + i * 16;
            cp16(VtB + d * 256 + ((sch ^ ((d & 7) << 1)) << 4),
                 vt + (size_t)d * LLen + kb + sch * 4);
        }
        CP_COMMIT();
    };

    // Q (already tf32-rounded in gmem)
    #pragma unroll
    for (int i = 0; i < 8; i++) {
        int r = srow + i * 16;
        cp16(QsB + r * 256 + ((sch ^ ((r & 7) << 1)) << 4),
             qg + (size_t)(q0 + r) * N3E + sch * 4);
    }
    load_kv(t0 * 64, t0 & 1);

    float m[2] = {-INFINITY, -INFINITY};
    float l[2] = {0.f, 0.f};
    float oacc[8][4];
    #pragma unroll
    for (int j = 0; j < 8; j++)
        #pragma unroll
        for (int k = 0; k < 4; k++) oacc[j][k] = 0.f;

    const int arow = (wid << 4) + (lane & 15);
    const int achk = (lane >> 4) & 1;
    const int asw  = (arow & 7) << 1;
    int brow[4];
    #pragma unroll
    for (int p = 0; p < 4; p++) brow[p] = (p << 4) + (lane & 7) + (((lane >> 4) & 1) << 3);
    const int bchk = (lane >> 3) & 1;

    const int srcA = (lane & ~3) | (t >> 1);
    const int srcB = srcA + 2;
    const bool odd = (t & 1);

    for (int ti = t0; ti < t1; ti++) {
        const int kb = ti * 64;
        const int buf = ti & 1;
        const uint32_t KsB = QsB + 32768u + (uint32_t)buf * 16384u;
        const uint32_t VtB = QsB + 65536u + (uint32_t)buf * 16384u;

        asm volatile("cp.async.wait_group 0;" ::: "memory");
        __syncthreads();
        if (ti + 1 < t1) load_kv(kb + 64, buf ^ 1);

        if (q0 + (wid << 4) + 15 < kb) continue;

        // ---- S = Q K^T ----
        float sacc[8][4];
        #pragma unroll
        for (int j = 0; j < 8; j++)
            #pragma unroll
            for (int k = 0; k < 4; k++) sacc[j][k] = 0.f;

        #pragma unroll
        for (int ks = 0; ks < 8; ks++) {
            uint32_t a0, a1, a2, a3;
            ldsm4(a0, a1, a2, a3,
                  QsB + arow * 256 + ((((ks << 1) + achk) ^ asw) << 4));
            uint32_t bf[8][2];
            #pragma unroll
            for (int p = 0; p < 4; p++)
                ldsm4(bf[2*p][0], bf[2*p][1], bf[2*p+1][0], bf[2*p+1][1],
                      KsB + brow[p] * 256 + ((((ks << 1) + bchk) ^ ((brow[p] & 7) << 1)) << 4));
            #pragma unroll
            for (int j = 0; j < 8; j++)
                mma_tf32(sacc[j], a0, a1, a2, a3, bf[j][0], bf[j][1]);
        }

        if (kb >= q0) {
            const int r0g = q0 + (wid << 4) + g;
            #pragma unroll
            for (int j = 0; j < 8; j++) {
                int cg = kb + (j << 3) + (t << 1);
                if (cg > r0g)         sacc[j][0] = -1e9f;
                if (cg + 1 > r0g)     sacc[j][1] = -1e9f;
                if (cg > r0g + 8)     sacc[j][2] = -1e9f;
                if (cg + 1 > r0g + 8) sacc[j][3] = -1e9f;
            }
        }

        // ---- online softmax (rows g and g+8); l summed over ROUNDED p ----
        float mt0 = -INFINITY, mt1 = -INFINITY;
        #pragma unroll
        for (int j = 0; j < 8; j++) {
            mt0 = fmaxf(mt0, fmaxf(sacc[j][0], sacc[j][1]));
            mt1 = fmaxf(mt1, fmaxf(sacc[j][2], sacc[j][3]));
        }
        mt0 = fmaxf(mt0, __shfl_xor_sync(0xffffffffu, mt0, 1));
        mt0 = fmaxf(mt0, __shfl_xor_sync(0xffffffffu, mt0, 2));
        mt1 = fmaxf(mt1, __shfl_xor_sync(0xffffffffu, mt1, 1));
        mt1 = fmaxf(mt1, __shfl_xor_sync(0xffffffffu, mt1, 2));
        float mn0 = fmaxf(m[0], mt0), mn1 = fmaxf(m[1], mt1);
        float sc0 = __expf(m[0] - mn0), sc1 = __expf(m[1] - mn1);
        m[0] = mn0; m[1] = mn1;
        float ls0 = 0.f, ls1 = 0.f;
        #pragma unroll
        for (int j = 0; j < 8; j++) {
            sacc[j][0] = rna(__expf(sacc[j][0] - mn0)); ls0 += sacc[j][0];
            sacc[j][1] = rna(__expf(sacc[j][1] - mn0)); ls0 += sacc[j][1];
            sacc[j][2] = rna(__expf(sacc[j][2] - mn1)); ls1 += sacc[j][2];
            sacc[j][3] = rna(__expf(sacc[j][3] - mn1)); ls1 += sacc[j][3];
        }
        ls0 += __shfl_xor_sync(0xffffffffu, ls0, 1);
        ls0 += __shfl_xor_sync(0xffffffffu, ls0, 2);
        ls1 += __shfl_xor_sync(0xffffffffu, ls1, 1);
        ls1 += __shfl_xor_sync(0xffffffffu, ls1, 2);
        l[0] = l[0] * sc0 + ls0;
        l[1] = l[1] * sc1 + ls1;
        #pragma unroll
        for (int j = 0; j < 8; j++) {
            oacc[j][0] *= sc0; oacc[j][1] *= sc0;
            oacc[j][2] *= sc1; oacc[j][3] *= sc1;
        }

        // ---- O += P V : P C-frag -> A-frag via shuffles, then MMA ----
        #pragma unroll
        for (int ks = 0; ks < 8; ks++) {
            float v0 = __shfl_sync(0xffffffffu, sacc[ks][0], srcA);
            float v1 = __shfl_sync(0xffffffffu, sacc[ks][1], srcA);
            float v2 = __shfl_sync(0xffffffffu, sacc[ks][2], srcA);
            float v3 = __shfl_sync(0xffffffffu, sacc[ks][3], srcA);
            float w0 = __shfl_sync(0xffffffffu, sacc[ks][0], srcB);
            float w1 = __shfl_sync(0xffffffffu, sacc[ks][1], srcB);
            float w2 = __shfl_sync(0xffffffffu, sacc[ks][2], srcB);
            float w3 = __shfl_sync(0xffffffffu, sacc[ks][3], srcB);
            uint32_t pa0 = __float_as_uint(odd ? v1 : v0);
            uint32_t pa1 = __float_as_uint(odd ? v3 : v2);
            uint32_t pa2 = __float_as_uint(odd ? w1 : w0);
            uint32_t pa3 = __float_as_uint(odd ? w3 : w2);

            uint32_t vf[8][2];
            #pragma unroll
            for (int p = 0; p < 4; p++)
                ldsm4(vf[2*p][0], vf[2*p][1], vf[2*p+1][0], vf[2*p+1][1],
                      VtB + brow[p] * 256 + ((((ks << 1) + bchk) ^ ((brow[p] & 7) << 1)) << 4));
            #pragma unroll
            for (int j = 0; j < 8; j++)
                mma_tf32(oacc[j], pa0, pa1, pa2, pa3, vf[j][0], vf[j][1]);
        }
    }

    const int lr0 = (wid << 4) + g;
    const int lr1 = lr0 + 8;
    if (split) {
        const int pidx = (bh * 8 + (qt - 8)) * 2 + ch;
        float* po = g_po + (size_t)pidx * 128 * 64;
        #pragma unroll
        for (int j = 0; j < 8; j++) {
            int d = (j << 3) + (t << 1);
            *(float2*)&po[lr0 * 64 + d] = make_float2(oacc[j][0], oacc[j][1]);
            *(float2*)&po[lr1 * 64 + d] = make_float2(oacc[j][2], oacc[j][3]);
        }
        if (t == 0) {
            g_pm[pidx * 128 + lr0] = m[0]; g_pl[pidx * 128 + lr0] = l[0];
            g_pm[pidx * 128 + lr1] = m[1]; g_pl[pidx * 128 + lr1] = l[1];
        }
    } else {
        const float inv0 = 1.f / l[0], inv1 = 1.f / l[1];
        const int grow = b * LLen + q0 + lr0;
        __nv_bfloat16* ah0 = g_ah + (size_t)grow * Ee + h * Dd;
        __nv_bfloat16* al0 = g_al + (size_t)grow * Ee + h * Dd;
        __nv_bfloat16* ah1 = ah0 + 8 * Ee;
        __nv_bfloat16* al1 = al0 + 8 * Ee;
        #pragma unroll
        for (int j = 0; j < 8; j++) {
            int d = (j << 3) + (t << 1);
            float o0 = oacc[j][0] * inv0, o1 = oacc[j][1] * inv0;
            float o2 = oacc[j][2] * inv1, o3 = oacc[j][3] * inv1;
            __nv_bfloat16 h0,l0b,h1,l1b,h2,l2b,h3,l3b;
            bf16_split(o0, h0, l0b); bf16_split(o1, h1, l1b);
            bf16_split(o2, h2, l2b); bf16_split(o3, h3, l3b);
            *(__nv_bfloat162*)&ah0[d] = __nv_bfloat162(h0, h1);
            *(__nv_bfloat162*)&al0[d] = __nv_bfloat162(l0b, l1b);
            *(__nv_bfloat162*)&ah1[d] = __nv_bfloat162(h2, h3);
            *(__nv_bfloat162*)&al1[d] = __nv_bfloat162(l2b, l3b);
        }
    }
}

// ---------------- merge split-KV partials ----------------
__global__ void merge_kv()
{
    const int s  = blockIdx.x;
    const int bh = blockIdx.y;
    const int qt = 8 + s;
    const int b = bh / Hh, h = bh - b * Hh;
    const int p0 = (bh * 8 + s) * 2;
    const int p1 = p0 + 1;
    const int r  = threadIdx.x >> 1;
    const int c0 = (threadIdx.x & 1) * 32;

    float m1 = g_pm[p0 * 128 + r], l1 = g_pl[p0 * 128 + r];
    float m2 = g_pm[p1 * 128 + r], l2 = g_pl[p1 * 128 + r];
    float mm = fmaxf(m1, m2);
    float e1 = __expf(m1 - mm), e2 = __expf(m2 - mm);
    float inv = 1.f / (l1 * e1 + l2 * e2);

    const float* o1 = g_po + ((size_t)p0 * 128 + r) * 64 + c0;
    const float* o2 = g_po + ((size_t)p1 * 128 + r) * 64 + c0;
    const int grow = b * LLen + qt * 128 + r;
    __nv_bfloat16* ah = g_ah + (size_t)grow * Ee + h * Dd + c0;
    __nv_bfloat16* al = g_al + (size_t)grow * Ee + h * Dd + c0;

    #pragma unroll
    for (int c = 0; c < 32; c += 2) {
        float2 a = *(const float2*)&o1[c];
        float2 bx = *(const float2*)&o2[c];
        float v0 = (a.x * e1 + bx.x * e2) * inv;
        float v1 = (a.y * e1 + bx.y * e2) * inv;
        __nv_bfloat16 h0, l0, h1, l1b;
        bf16_split(v0, h0, l0); bf16_split(v1, h1, l1b);
        *(__nv_bfloat162*)&ah[c] = __nv_bfloat162(h0, h1);
        *(__nv_bfloat162*)&al[c] = __nv_bfloat162(l0, l1b);
    }
}

// ---------------- launch ----------------
extern "C" void kernel_launch(void* const* d_in, const int* in_sizes, int n_in,
                              void* d_out, int out_size)
{
    const float* x     = (const float*)d_in[0];
    const float* w_in  = (const float*)d_in[1];
    const float* b_in  = (const float*)d_in[2];
    const float* A_in  = (const float*)d_in[3];
    const float* B_in  = (const float*)d_in[4];
    const float* w_out = (const float*)d_in[5];
    const float* b_out = (const float*)d_in[6];
    const float* A_out = (const float*)d_in[7];
    const float* B_out = (const float*)d_in[8];
    float* out = (float*)d_out;

    __nv_bfloat16 *p_w1h, *p_w1l, *p_w2h, *p_w2l, *p_xh, *p_xl, *p_ah, *p_al;
    float *p_c;
    cudaGetSymbolAddress((void**)&p_w1h, g_w1h);
    cudaGetSymbolAddress((void**)&p_w1l, g_w1l);
    cudaGetSymbolAddress((void**)&p_w2h, g_w2h);
    cudaGetSymbolAddress((void**)&p_w2l, g_w2l);
    cudaGetSymbolAddress((void**)&p_xh,  g_xh);
    cudaGetSymbolAddress((void**)&p_xl,  g_xl);
    cudaGetSymbolAddress((void**)&p_c,   g_c);
    cudaGetSymbolAddress((void**)&p_ah,  g_ah);
    cudaGetSymbolAddress((void**)&p_al,  g_al);

    const int smem1 = 3 * (2 * 128 * 64 + 2 * 128 * 64);   // 98304 (>= 66048 for v-transpose)
    const int smem2 = 4 * (2 * 128 * 64 + 2 * 64 * 64);    // 98304
    const int smemF = 98304;                                // Q + 2K + 2V
    cudaFuncSetAttribute((const void*)gemm_tc1,
                         cudaFuncAttributeMaxDynamicSharedMemorySize, smem1);
    cudaFuncSetAttribute((const void*)gemm_tc2,
                         cudaFuncAttributeMaxDynamicSharedMemorySize, smem2);
    cudaFuncSetAttribute((const void*)flash_tc,
                         cudaFuncAttributeMaxDynamicSharedMemorySize, smemF);

    {
        dim3 blk(32, 8);
        dim3 gp(N3E / 32, Ee / 32, 2);
        prep_wt2<<<gp, blk>>>(w_in, A_in, B_in, p_w1h, p_w1l,
                              w_out, A_out, B_out, p_w2h, p_w2l);
        cvt_x<<<Mrows * Ee / 4 / 256, 256>>>((const float4*)x, p_xh, p_xl);
    }
    {
        dim3 grid(N3E / 128, Mrows / 128);
        gemm_tc1<<<grid, 256, smem1>>>(p_xh, p_xl, p_w1h, p_w1l, b_in, p_c, N3E);
    }
    {
        dim3 grid(Bb * Hh, 24);
        flash_tc<<<grid, 256, smemF>>>();
        merge_kv<<<dim3(8, Bb * Hh), 256>>>();
    }
    {
        dim3 grid(Ee / 64, Mrows / 128);
        gemm_tc2<<<grid, 256, smem2>>>(p_ah, p_al, p_w2h, p_w2l, b_out, out, Ee);
    }
}